// round 1
// baseline (speedup 1.0000x reference)
#include <cuda_runtime.h>
#include <cstdint>
#include <math.h>

// ----------------------------------------------------------------------------
// SimplePINN forward on GB300
//   pass1: layer0 GEMM (feats@W0^T+b0) -> y scratch + per-block sum(y^2)
//   reduce: deterministic fixed-order sum of block partials -> g_sumsq
//   pass2: noise(threefry)+tanh, 3x (128x128 GEMM + tanh), output layer
// ----------------------------------------------------------------------------

#define TPB 256
#define ROWS_PER_BLK 64
#define NPOINTS 1000000
#define NBLK (NPOINTS / ROWS_PER_BLK)   // 15625
#define HDIM 128
#define KPAD 132                         // padded K stride (floats)
#define P1_SMEM (25728 * 4 + 64)
#define P2_SMEM (25728 * 4)

__device__ float  g_y[(size_t)HDIM * NPOINTS];   // 512 MB scratch for layer-0 output
__device__ double g_part[NBLK];
__device__ double g_sumsq;

extern __shared__ float smem[];

// ---------------------------------------------------------------- threefry ---
__device__ __forceinline__ uint32_t rotl32(uint32_t x, int r) {
    return __funnelshift_l(x, x, r);
}

// jax partitionable random bits for key (0,42), flat index idx:
//   (o0,o1) = threefry2x32(key, x0=hi(idx)=0, x1=lo(idx)=idx); bits = o0 ^ o1
__device__ __forceinline__ uint32_t threefry_bits(uint32_t idx) {
    const uint32_t k0 = 0u, k1 = 42u;
    const uint32_t k2 = k0 ^ k1 ^ 0x1BD11BDAu;
    uint32_t x0 = 0u + k0;
    uint32_t x1 = idx + k1;
#define TFR(r) { x0 += x1; x1 = rotl32(x1, r); x1 ^= x0; }
    TFR(13) TFR(15) TFR(26) TFR(6)   x0 += k1; x1 += k2 + 1u;
    TFR(17) TFR(29) TFR(16) TFR(24)  x0 += k2; x1 += k0 + 2u;
    TFR(13) TFR(15) TFR(26) TFR(6)   x0 += k0; x1 += k1 + 3u;
    TFR(17) TFR(29) TFR(16) TFR(24)  x0 += k1; x1 += k2 + 4u;
    TFR(13) TFR(15) TFR(26) TFR(6)   x0 += k2; x1 += k0 + 5u;
#undef TFR
    return x0 ^ x1;
}

// XLA ErfInv32 polynomial (matches chlo decomposition used by jax)
__device__ __forceinline__ float erfinv_xla(float x) {
    float w = -log1pf(-x * x);
    float p;
    if (w < 5.0f) {
        w -= 2.5f;
        p = 2.81022636e-08f;
        p = fmaf(p, w, 3.43273939e-07f);
        p = fmaf(p, w, -3.5233877e-06f);
        p = fmaf(p, w, -4.39150654e-06f);
        p = fmaf(p, w, 0.00021858087f);
        p = fmaf(p, w, -0.00125372503f);
        p = fmaf(p, w, -0.00417768164f);
        p = fmaf(p, w, 0.246640727f);
        p = fmaf(p, w, 1.50140941f);
    } else {
        w = sqrtf(w) - 3.0f;
        p = -0.000200214257f;
        p = fmaf(p, w, 0.000100950558f);
        p = fmaf(p, w, 0.00134934322f);
        p = fmaf(p, w, -0.00367342844f);
        p = fmaf(p, w, 0.00573950773f);
        p = fmaf(p, w, -0.0076224613f);
        p = fmaf(p, w, 0.00943887047f);
        p = fmaf(p, w, 1.00167406f);
        p = fmaf(p, w, 2.83297682f);
    }
    return p * x;
}

__device__ __forceinline__ float noise_at(uint32_t flat) {
    uint32_t bits = threefry_bits(flat);
    float u01 = __uint_as_float((bits >> 9) | 0x3F800000u) - 1.0f;  // [0,1)
    const float lo = -0.99999994f;                                   // nextafter(-1,0)
    float u = fmaxf(lo, fmaf(u01, 1.99999994f, lo));                 // uniform(lo, 1)
    return 1.4142135381698608f * erfinv_xla(u);                      // sqrt(2)*erfinv
}

// --------------------------------------------------------------- GEMM tile ---
// 64 rows x 128 cols out of SMEM; thread micro-tile = 8 rows x 4 cols.
// lanes 0..7 -> adjacent rows (stride KPAD=132 floats -> bank step 4, conflict
// free for LDS.128); weight reads are quarter-warp broadcasts.
template <int KK4>
__device__ __forceinline__ void gemm_tile(const float* sW, const float* sA,
                                          float acc[8][4], int tid) {
    const float4* Wv = (const float4*)sW;
    const float4* Av = (const float4*)sA;
    const int j0 = (tid >> 3) << 2;  // output col base (0..124)
    const int rs = tid & 7;          // row slot
#pragma unroll 4
    for (int k4 = 0; k4 < KK4; ++k4) {
        float4 w0 = Wv[(j0 + 0) * 33 + k4];
        float4 w1 = Wv[(j0 + 1) * 33 + k4];
        float4 w2 = Wv[(j0 + 2) * 33 + k4];
        float4 w3 = Wv[(j0 + 3) * 33 + k4];
#pragma unroll
        for (int i = 0; i < 8; ++i) {
            float4 a = Av[(rs + (i << 3)) * 33 + k4];
            acc[i][0] = fmaf(a.x, w0.x, fmaf(a.y, w0.y, fmaf(a.z, w0.z, fmaf(a.w, w0.w, acc[i][0]))));
            acc[i][1] = fmaf(a.x, w1.x, fmaf(a.y, w1.y, fmaf(a.z, w1.z, fmaf(a.w, w1.w, acc[i][1]))));
            acc[i][2] = fmaf(a.x, w2.x, fmaf(a.y, w2.y, fmaf(a.z, w2.z, fmaf(a.w, w2.w, acc[i][2]))));
            acc[i][3] = fmaf(a.x, w3.x, fmaf(a.y, w3.y, fmaf(a.z, w3.z, fmaf(a.w, w3.w, acc[i][3]))));
        }
    }
}

// ------------------------------------------------------------------- pass1 ---
__global__ void __launch_bounds__(TPB, 2)
pass1_kernel(const float* __restrict__ X, const float* __restrict__ FB,
             const float* __restrict__ W0, const float* __restrict__ b0) {
    float*  sW   = smem;           // 128 x 132
    float*  sF   = smem + 16896;   // 64 x 132  (feats, cols 130/131 zero)
    float*  sX   = smem + 25344;   // 64 x 2
    float*  sB   = smem + 25472;   // fourier_B (2 x 64)
    float*  sb   = smem + 25600;   // b0
    double* sRed = (double*)(smem + 25728);

    const int tid = threadIdx.x;
    const int r0  = blockIdx.x * ROWS_PER_BLK;

    if (tid < 128) {
        sX[tid] = X[r0 * 2 + tid];
        sB[tid] = FB[tid];
        sb[tid] = b0[tid];
    }
    for (int idx = tid; idx < 128 * 130; idx += TPB) {
        int j = idx / 130;
        int k = idx - j * 130;
        sW[j * KPAD + k] = W0[idx];
    }
    if (tid < 128) {                       // zero the pad columns
        sW[tid * KPAD + 130] = 0.0f;
        sW[tid * KPAD + 131] = 0.0f;
    }
    __syncthreads();

    // feats = [x, sin(2*pi*t), cos(2*pi*t)]; use period-1 identity: sinpi(2*frac(t))
    for (int idx = tid; idx < ROWS_PER_BLK * KPAD; idx += TPB) {
        int r = idx / KPAD;
        int k = idx - r * KPAD;
        float v;
        if (k < 2) {
            v = sX[r * 2 + k];
        } else if (k < 130) {
            int j = (k < 66) ? (k - 2) : (k - 66);
            float t  = fmaf(sX[r * 2 + 1], sB[64 + j], sX[r * 2] * sB[j]);
            float fr = t - rintf(t);
            v = (k < 66) ? sinpif(2.0f * fr) : cospif(2.0f * fr);
        } else {
            v = 0.0f;
        }
        sF[idx] = v;
    }
    __syncthreads();

    float acc[8][4] = {};
    gemm_tile<33>(sW, sF, acc, tid);

    const int j0 = (tid >> 3) << 2;
    const int rs = tid & 7;
    double lsum = 0.0;
#pragma unroll
    for (int i = 0; i < 8; ++i) {
        float4 y;
        y.x = acc[i][0] + sb[j0 + 0];
        y.y = acc[i][1] + sb[j0 + 1];
        y.z = acc[i][2] + sb[j0 + 2];
        y.w = acc[i][3] + sb[j0 + 3];
        lsum += (double)y.x * y.x + (double)y.y * y.y +
                (double)y.z * y.z + (double)y.w * y.w;
        int gr = r0 + rs + (i << 3);
        *(float4*)(&g_y[(size_t)gr * HDIM + j0]) = y;
    }

    const unsigned lane = tid & 31, warp = tid >> 5;
#pragma unroll
    for (int off = 16; off; off >>= 1)
        lsum += __shfl_down_sync(0xffffffffu, lsum, off);
    if (lane == 0) sRed[warp] = lsum;
    __syncthreads();
    if (warp == 0) {
        double v = (lane < 8) ? sRed[lane] : 0.0;
#pragma unroll
        for (int off = 4; off; off >>= 1)
            v += __shfl_down_sync(0xffffffffu, v, off);
        if (lane == 0) g_part[blockIdx.x] = v;
    }
}

// ------------------------------------------------------- deterministic sum ---
__global__ void reduce_kernel() {
    __shared__ double s[TPB];
    double v = 0.0;
    for (int i = threadIdx.x; i < NBLK; i += TPB) v += g_part[i];
    s[threadIdx.x] = v;
    __syncthreads();
    for (int o = TPB / 2; o > 0; o >>= 1) {
        if (threadIdx.x < o) s[threadIdx.x] += s[threadIdx.x + o];
        __syncthreads();
    }
    if (threadIdx.x == 0) g_sumsq = s[0];
}

// ------------------------------------------------------------------- pass2 ---
__global__ void __launch_bounds__(TPB, 2)
pass2_kernel(const float* __restrict__ W1, const float* __restrict__ b1,
             const float* __restrict__ W2, const float* __restrict__ b2,
             const float* __restrict__ W3, const float* __restrict__ b3,
             const float* __restrict__ W4, const float* __restrict__ b4,
             float* __restrict__ out) {
    float* sW  = smem;           // 128 x 132
    float* sH  = smem + 16896;   // 64 x 132
    float* sB  = smem + 25344;   // bias
    float* sW4 = smem + 25472;   // 2 x 128

    const int tid = threadIdx.x;
    const int r0  = blockIdx.x * ROWS_PER_BLK;

    double ss   = g_sumsq;
    float power = (float)(ss * (1.0 / 128000000.0));
    float stdv  = 0.0f;
    if (isfinite(power) && power > 1.1920929e-07f) stdv = sqrtf(power * 1e-3f);

    sW4[tid] = W4[tid & 255];  // 256 entries, TPB==256

    // noise + tanh of layer 0
    for (int e = tid; e < ROWS_PER_BLK * HDIM; e += TPB) {
        uint32_t f = (uint32_t)(r0 * HDIM + e);
        float n = noise_at(f);
        float y = g_y[f];
        int r = e >> 7, c = e & 127;
        sH[r * KPAD + c] = tanhf(fmaf(n, stdv, y));
    }
    __syncthreads();

    const float* Ws[3] = {W1, W2, W3};
    const float* bs[3] = {b1, b2, b3};
    const int j0 = (tid >> 3) << 2;
    const int rs = tid & 7;

#pragma unroll 1
    for (int L = 0; L < 3; ++L) {
        const float* W = Ws[L];
        for (int idx = tid; idx < 128 * 128; idx += TPB)
            sW[(idx >> 7) * KPAD + (idx & 127)] = W[idx];
        if (tid < 128) sB[tid] = bs[L][tid];
        __syncthreads();

        float acc[8][4] = {};
        gemm_tile<32>(sW, sH, acc, tid);
        __syncthreads();  // all reads of sH complete before overwrite

#pragma unroll
        for (int i = 0; i < 8; ++i) {
            float4 h;
            h.x = tanhf(acc[i][0] + sB[j0 + 0]);
            h.y = tanhf(acc[i][1] + sB[j0 + 1]);
            h.z = tanhf(acc[i][2] + sB[j0 + 2]);
            h.w = tanhf(acc[i][3] + sB[j0 + 3]);
            *(float4*)(&sH[(rs + (i << 3)) * KPAD + j0]) = h;
        }
        __syncthreads();
    }

    // output layer: 64 rows x 2 cols
    if (tid < 128) {
        int r = tid >> 1, o = tid & 1;
        const float* hrow = &sH[r * KPAD];
        const float* w    = &sW4[o * HDIM];
        float acc = b4[o];
#pragma unroll 8
        for (int k = 0; k < HDIM; ++k) acc = fmaf(hrow[k], w[k], acc);
        out[(r0 + r) * 2 + o] = acc;
    }
}

// ------------------------------------------------------------------- host ----
extern "C" void kernel_launch(void* const* d_in, const int* in_sizes, int n_in,
                              void* d_out, int out_size) {
    const float* X  = (const float*)d_in[0];
    const float* FB = (const float*)d_in[1];
    const float* W0 = (const float*)d_in[2];
    const float* b0 = (const float*)d_in[3];
    const float* W1 = (const float*)d_in[4];
    const float* b1 = (const float*)d_in[5];
    const float* W2 = (const float*)d_in[6];
    const float* b2 = (const float*)d_in[7];
    const float* W3 = (const float*)d_in[8];
    const float* b3 = (const float*)d_in[9];
    const float* W4 = (const float*)d_in[10];
    const float* b4 = (const float*)d_in[11];
    float* out = (float*)d_out;

    cudaFuncSetAttribute(pass1_kernel, cudaFuncAttributeMaxDynamicSharedMemorySize, P1_SMEM);
    cudaFuncSetAttribute(pass2_kernel, cudaFuncAttributeMaxDynamicSharedMemorySize, P2_SMEM);

    pass1_kernel<<<NBLK, TPB, P1_SMEM>>>(X, FB, W0, b0);
    reduce_kernel<<<1, TPB>>>();
    pass2_kernel<<<NBLK, TPB, P2_SMEM>>>(W1, b1, W2, b2, W3, b3, W4, b4, out);
}

// round 2
// speedup vs baseline: 1.0558x; 1.0558x over previous
#include <cuda_runtime.h>
#include <cstdint>
#include <math.h>

// ----------------------------------------------------------------------------
// SimplePINN forward on GB300
//   pass1: layer0 GEMM (feats@W0^T+b0) -> y scratch + per-block sum(y^2)
//   reduce: deterministic fixed-order sum of block partials -> g_sumsq
//   pass2: noise(threefry)+tanh, 3x (128x128 GEMM + tanh), output layer
// R2: GEMM inner loops use packed fp32x2 FMA (SASS FFMA2) with k-parity
//     packed accumulators -> half the FMA-pipe issue slots.
// ----------------------------------------------------------------------------

#define TPB 256
#define ROWS_PER_BLK 64
#define NPOINTS 1000000
#define NBLK (NPOINTS / ROWS_PER_BLK)   // 15625
#define HDIM 128
#define KPAD 132                         // padded K stride (floats)
#define P1_SMEM (25728 * 4 + 64)
#define P2_SMEM (25728 * 4)

__device__ float  g_y[(size_t)HDIM * NPOINTS];   // 512 MB scratch for layer-0 output
__device__ double g_part[NBLK];
__device__ double g_sumsq;

extern __shared__ float smem[];

typedef unsigned long long u64;

// ------------------------------------------------------------- f32x2 FMA ----
__device__ __forceinline__ void ffma2(u64& d, u64 a, u64 b) {
    asm("fma.rn.f32x2 %0, %1, %2, %0;" : "+l"(d) : "l"(a), "l"(b));
}
__device__ __forceinline__ float fold2(u64 v) {
    float lo = __uint_as_float((unsigned)(v & 0xffffffffu));
    float hi = __uint_as_float((unsigned)(v >> 32));
    return lo + hi;
}

// ---------------------------------------------------------------- threefry ---
__device__ __forceinline__ uint32_t rotl32(uint32_t x, int r) {
    return __funnelshift_l(x, x, r);
}

// jax partitionable random bits for key (0,42), flat index idx:
//   (o0,o1) = threefry2x32(key, x0=hi(idx)=0, x1=lo(idx)=idx); bits = o0 ^ o1
__device__ __forceinline__ uint32_t threefry_bits(uint32_t idx) {
    const uint32_t k0 = 0u, k1 = 42u;
    const uint32_t k2 = k0 ^ k1 ^ 0x1BD11BDAu;
    uint32_t x0 = 0u + k0;
    uint32_t x1 = idx + k1;
#define TFR(r) { x0 += x1; x1 = rotl32(x1, r); x1 ^= x0; }
    TFR(13) TFR(15) TFR(26) TFR(6)   x0 += k1; x1 += k2 + 1u;
    TFR(17) TFR(29) TFR(16) TFR(24)  x0 += k2; x1 += k0 + 2u;
    TFR(13) TFR(15) TFR(26) TFR(6)   x0 += k0; x1 += k1 + 3u;
    TFR(17) TFR(29) TFR(16) TFR(24)  x0 += k1; x1 += k2 + 4u;
    TFR(13) TFR(15) TFR(26) TFR(6)   x0 += k2; x1 += k0 + 5u;
#undef TFR
    return x0 ^ x1;
}

// XLA ErfInv32 polynomial (matches chlo decomposition used by jax)
__device__ __forceinline__ float erfinv_xla(float x) {
    float w = -log1pf(-x * x);
    float p;
    if (w < 5.0f) {
        w -= 2.5f;
        p = 2.81022636e-08f;
        p = fmaf(p, w, 3.43273939e-07f);
        p = fmaf(p, w, -3.5233877e-06f);
        p = fmaf(p, w, -4.39150654e-06f);
        p = fmaf(p, w, 0.00021858087f);
        p = fmaf(p, w, -0.00125372503f);
        p = fmaf(p, w, -0.00417768164f);
        p = fmaf(p, w, 0.246640727f);
        p = fmaf(p, w, 1.50140941f);
    } else {
        w = sqrtf(w) - 3.0f;
        p = -0.000200214257f;
        p = fmaf(p, w, 0.000100950558f);
        p = fmaf(p, w, 0.00134934322f);
        p = fmaf(p, w, -0.00367342844f);
        p = fmaf(p, w, 0.00573950773f);
        p = fmaf(p, w, -0.0076224613f);
        p = fmaf(p, w, 0.00943887047f);
        p = fmaf(p, w, 1.00167406f);
        p = fmaf(p, w, 2.83297682f);
    }
    return p * x;
}

__device__ __forceinline__ float noise_at(uint32_t flat) {
    uint32_t bits = threefry_bits(flat);
    float u01 = __uint_as_float((bits >> 9) | 0x3F800000u) - 1.0f;  // [0,1)
    const float lo = -0.99999994f;                                   // nextafter(-1,0)
    float u = fmaxf(lo, fmaf(u01, 1.99999994f, lo));                 // uniform(lo, 1)
    return 1.4142135381698608f * erfinv_xla(u);                      // sqrt(2)*erfinv
}

// --------------------------------------------------------------- GEMM tile ---
// 64 rows x 128 cols out of SMEM; thread micro-tile = 8 rows x 4 cols.
// Packed f32x2 accumulators: lo half sums even-k products, hi half odd-k;
// a float4 SMEM load supplies two f32x2 operands directly (no packing ops).
// lanes 0..7 -> adjacent rows (stride KPAD=132 floats -> bank step 4, conflict
// free for LDS.128); weight reads are quarter-warp broadcasts.
template <int KK4>
__device__ __forceinline__ void gemm_tile2(const float* sW, const float* sA,
                                           u64 acc[8][4], int tid) {
    const ulonglong2* Wv = (const ulonglong2*)sW;
    const ulonglong2* Av = (const ulonglong2*)sA;
    const int j0 = (tid >> 3) << 2;  // output col base (0..124)
    const int rs = tid & 7;          // row slot
#pragma unroll 3
    for (int k4 = 0; k4 < KK4; ++k4) {
        ulonglong2 w0 = Wv[(j0 + 0) * 33 + k4];
        ulonglong2 w1 = Wv[(j0 + 1) * 33 + k4];
        ulonglong2 w2 = Wv[(j0 + 2) * 33 + k4];
        ulonglong2 w3 = Wv[(j0 + 3) * 33 + k4];
#pragma unroll
        for (int i = 0; i < 8; ++i) {
            ulonglong2 a = Av[(rs + (i << 3)) * 33 + k4];
            ffma2(acc[i][0], a.x, w0.x);
            ffma2(acc[i][1], a.x, w1.x);
            ffma2(acc[i][2], a.x, w2.x);
            ffma2(acc[i][3], a.x, w3.x);
            ffma2(acc[i][0], a.y, w0.y);
            ffma2(acc[i][1], a.y, w1.y);
            ffma2(acc[i][2], a.y, w2.y);
            ffma2(acc[i][3], a.y, w3.y);
        }
    }
}

// ------------------------------------------------------------------- pass1 ---
__global__ void __launch_bounds__(TPB, 2)
pass1_kernel(const float* __restrict__ X, const float* __restrict__ FB,
             const float* __restrict__ W0, const float* __restrict__ b0) {
    float*  sW   = smem;           // 128 x 132
    float*  sF   = smem + 16896;   // 64 x 132  (feats, cols 130/131 zero)
    float*  sX   = smem + 25344;   // 64 x 2
    float*  sB   = smem + 25472;   // fourier_B (2 x 64)
    float*  sb   = smem + 25600;   // b0
    double* sRed = (double*)(smem + 25728);

    const int tid = threadIdx.x;
    const int r0  = blockIdx.x * ROWS_PER_BLK;

    if (tid < 128) {
        sX[tid] = X[r0 * 2 + tid];
        sB[tid] = FB[tid];
        sb[tid] = b0[tid];
    }
    for (int idx = tid; idx < 128 * 130; idx += TPB) {
        int j = idx / 130;
        int k = idx - j * 130;
        sW[j * KPAD + k] = W0[idx];
    }
    if (tid < 128) {                       // zero the pad columns
        sW[tid * KPAD + 130] = 0.0f;
        sW[tid * KPAD + 131] = 0.0f;
    }
    __syncthreads();

    // feats = [x, sin(2*pi*t), cos(2*pi*t)]; use period-1 identity: sinpi(2*frac(t))
    for (int idx = tid; idx < ROWS_PER_BLK * KPAD; idx += TPB) {
        int r = idx / KPAD;
        int k = idx - r * KPAD;
        float v;
        if (k < 2) {
            v = sX[r * 2 + k];
        } else if (k < 130) {
            int j = (k < 66) ? (k - 2) : (k - 66);
            float t  = fmaf(sX[r * 2 + 1], sB[64 + j], sX[r * 2] * sB[j]);
            float fr = t - rintf(t);
            v = (k < 66) ? sinpif(2.0f * fr) : cospif(2.0f * fr);
        } else {
            v = 0.0f;
        }
        sF[idx] = v;
    }
    __syncthreads();

    u64 acc[8][4] = {};
    gemm_tile2<33>(sW, sF, acc, tid);

    const int j0 = (tid >> 3) << 2;
    const int rs = tid & 7;
    double lsum = 0.0;
#pragma unroll
    for (int i = 0; i < 8; ++i) {
        float4 y;
        y.x = fold2(acc[i][0]) + sb[j0 + 0];
        y.y = fold2(acc[i][1]) + sb[j0 + 1];
        y.z = fold2(acc[i][2]) + sb[j0 + 2];
        y.w = fold2(acc[i][3]) + sb[j0 + 3];
        lsum += (double)y.x * y.x + (double)y.y * y.y +
                (double)y.z * y.z + (double)y.w * y.w;
        int gr = r0 + rs + (i << 3);
        *(float4*)(&g_y[(size_t)gr * HDIM + j0]) = y;
    }

    const unsigned lane = tid & 31, warp = tid >> 5;
#pragma unroll
    for (int off = 16; off; off >>= 1)
        lsum += __shfl_down_sync(0xffffffffu, lsum, off);
    if (lane == 0) sRed[warp] = lsum;
    __syncthreads();
    if (warp == 0) {
        double v = (lane < 8) ? sRed[lane] : 0.0;
#pragma unroll
        for (int off = 4; off; off >>= 1)
            v += __shfl_down_sync(0xffffffffu, v, off);
        if (lane == 0) g_part[blockIdx.x] = v;
    }
}

// ------------------------------------------------------- deterministic sum ---
__global__ void reduce_kernel() {
    __shared__ double s[TPB];
    double v = 0.0;
    for (int i = threadIdx.x; i < NBLK; i += TPB) v += g_part[i];
    s[threadIdx.x] = v;
    __syncthreads();
    for (int o = TPB / 2; o > 0; o >>= 1) {
        if (threadIdx.x < o) s[threadIdx.x] += s[threadIdx.x + o];
        __syncthreads();
    }
    if (threadIdx.x == 0) g_sumsq = s[0];
}

// ------------------------------------------------------------------- pass2 ---
__global__ void __launch_bounds__(TPB, 2)
pass2_kernel(const float* __restrict__ W1, const float* __restrict__ b1,
             const float* __restrict__ W2, const float* __restrict__ b2,
             const float* __restrict__ W3, const float* __restrict__ b3,
             const float* __restrict__ W4, const float* __restrict__ b4,
             float* __restrict__ out) {
    float* sW  = smem;           // 128 x 132
    float* sH  = smem + 16896;   // 64 x 132
    float* sB  = smem + 25344;   // bias
    float* sW4 = smem + 25472;   // 2 x 128

    const int tid = threadIdx.x;
    const int r0  = blockIdx.x * ROWS_PER_BLK;

    double ss   = g_sumsq;
    float power = (float)(ss * (1.0 / 128000000.0));
    float stdv  = 0.0f;
    if (isfinite(power) && power > 1.1920929e-07f) stdv = sqrtf(power * 1e-3f);

    sW4[tid] = W4[tid & 255];  // 256 entries, TPB==256

    // noise + tanh of layer 0
    for (int e = tid; e < ROWS_PER_BLK * HDIM; e += TPB) {
        uint32_t f = (uint32_t)(r0 * HDIM + e);
        float n = noise_at(f);
        float y = g_y[f];
        int r = e >> 7, c = e & 127;
        sH[r * KPAD + c] = tanhf(fmaf(n, stdv, y));
    }
    __syncthreads();

    const float* Ws[3] = {W1, W2, W3};
    const float* bs[3] = {b1, b2, b3};
    const int j0 = (tid >> 3) << 2;
    const int rs = tid & 7;

#pragma unroll 1
    for (int L = 0; L < 3; ++L) {
        const float* W = Ws[L];
        for (int idx = tid; idx < 128 * 128; idx += TPB)
            sW[(idx >> 7) * KPAD + (idx & 127)] = W[idx];
        if (tid < 128) sB[tid] = bs[L][tid];
        __syncthreads();

        u64 acc[8][4] = {};
        gemm_tile2<32>(sW, sH, acc, tid);
        __syncthreads();  // all reads of sH complete before overwrite

#pragma unroll
        for (int i = 0; i < 8; ++i) {
            float4 h;
            h.x = tanhf(fold2(acc[i][0]) + sB[j0 + 0]);
            h.y = tanhf(fold2(acc[i][1]) + sB[j0 + 1]);
            h.z = tanhf(fold2(acc[i][2]) + sB[j0 + 2]);
            h.w = tanhf(fold2(acc[i][3]) + sB[j0 + 3]);
            *(float4*)(&sH[(rs + (i << 3)) * KPAD + j0]) = h;
        }
        __syncthreads();
    }

    // output layer: 64 rows x 2 cols, packed f32x2 dot products
    if (tid < 128) {
        int r = tid >> 1, o = tid & 1;
        const u64* hrow = (const u64*)&sH[r * KPAD];
        const u64* w    = (const u64*)&sW4[o * HDIM];
        u64 a2 = 0;
#pragma unroll 16
        for (int k = 0; k < HDIM / 2; ++k) ffma2(a2, hrow[k], w[k]);
        out[(r0 + r) * 2 + o] = fold2(a2) + b4[o];
    }
}

// ------------------------------------------------------------------- host ----
extern "C" void kernel_launch(void* const* d_in, const int* in_sizes, int n_in,
                              void* d_out, int out_size) {
    const float* X  = (const float*)d_in[0];
    const float* FB = (const float*)d_in[1];
    const float* W0 = (const float*)d_in[2];
    const float* b0 = (const float*)d_in[3];
    const float* W1 = (const float*)d_in[4];
    const float* b1 = (const float*)d_in[5];
    const float* W2 = (const float*)d_in[6];
    const float* b2 = (const float*)d_in[7];
    const float* W3 = (const float*)d_in[8];
    const float* b3 = (const float*)d_in[9];
    const float* W4 = (const float*)d_in[10];
    const float* b4 = (const float*)d_in[11];
    float* out = (float*)d_out;

    cudaFuncSetAttribute(pass1_kernel, cudaFuncAttributeMaxDynamicSharedMemorySize, P1_SMEM);
    cudaFuncSetAttribute(pass2_kernel, cudaFuncAttributeMaxDynamicSharedMemorySize, P2_SMEM);

    pass1_kernel<<<NBLK, TPB, P1_SMEM>>>(X, FB, W0, b0);
    reduce_kernel<<<1, TPB>>>();
    pass2_kernel<<<NBLK, TPB, P2_SMEM>>>(W1, b1, W2, b2, W3, b3, W4, b4, out);
}

// round 4
// speedup vs baseline: 1.6054x; 1.5206x over previous
#include <cuda_runtime.h>
#include <cuda_bf16.h>
#include <cstdint>
#include <math.h>

// ----------------------------------------------------------------------------
// SimplePINN forward on GB300 (base sm_103 target) — HMMA mma.sync bf16
// split-2 GEMMs, 3-pass:
//   prep : W0..W3 -> padded bf16 hi/lo images in global scratch
//   pass1: feats -> SMEM bf16 hi/lo, mma vs W0 -> y scratch + sum(y^2)
//   reduce: deterministic sum -> g_sumsq
//   pass2: noise+tanh -> SMEM, 3x (mma + tanh), output layer in registers
// ----------------------------------------------------------------------------

#define NPOINTS 1000000
#define NBLK    7813          // ceil(1e6/128)
#define TPB     256

#define K1S 152               // pass1 k-stride in bf16 (K=144 padded, 19x16B rows)
#define K2S 136               // pass2 k-stride in bf16 (K=128 padded, 17x16B rows)

// pass1 smem layout (bytes)
#define P1_RED  0             // 8 doubles
#define P1_B0   64            // 128 f
#define P1_FB   576           // 128 f
#define P1_A    1152          // A_hi (38912) then A_lo (38912)
#define P1_W    78976         // W_hi (38912) then W_lo (38912)
#define P1_SMEM 156800
// pass2 smem layout
#define P2_BIAS 0             // 384 f
#define P2_W4   1536          // 256 f
#define P2_B4   2560          // 2 f
#define P2_W    2688          // W_hi (34816) then W_lo (34816)
#define P2_A    72320         // A_hi (34816) then A_lo (34816)
#define P2_SMEM 141952

__device__ __align__(16) __nv_bfloat16 g_w0img[2][128 * K1S];
__device__ __align__(16) __nv_bfloat16 g_wimg[3][2][128 * K2S];
__device__ float  g_y[(size_t)NBLK * 16384];     // accumulator-ownership layout
__device__ double g_part[NBLK];
__device__ double g_sumsq;

extern __shared__ __align__(16) char smem[];

// ------------------------------------------------------------ ptx helpers ---
__device__ __forceinline__ uint32_t smem_u32(const void* p) {
    uint32_t a;
    asm("{ .reg .u64 t; cvta.to.shared.u64 t, %1; cvt.u32.u64 %0, t; }" : "=r"(a) : "l"(p));
    return a;
}
__device__ __forceinline__ void ldsm_x4(uint32_t addr, uint32_t r[4]) {
    asm volatile("ldmatrix.sync.aligned.m8n8.x4.shared.b16 {%0,%1,%2,%3}, [%4];"
                 : "=r"(r[0]), "=r"(r[1]), "=r"(r[2]), "=r"(r[3]) : "r"(addr));
}
__device__ __forceinline__ void mma_bf16(float* c, const uint32_t* a, uint32_t b0, uint32_t b1) {
    asm volatile("mma.sync.aligned.m16n8k16.row.col.f32.bf16.bf16.f32 "
                 "{%0,%1,%2,%3}, {%4,%5,%6,%7}, {%8,%9}, {%0,%1,%2,%3};"
                 : "+f"(c[0]), "+f"(c[1]), "+f"(c[2]), "+f"(c[3])
                 : "r"(a[0]), "r"(a[1]), "r"(a[2]), "r"(a[3]), "r"(b0), "r"(b1));
}

// ---------------------------------------------------------------- threefry ---
__device__ __forceinline__ uint32_t rotl32(uint32_t x, int r) { return __funnelshift_l(x, x, r); }
__device__ __forceinline__ uint32_t threefry_bits(uint32_t idx) {
    const uint32_t k0 = 0u, k1 = 42u;
    const uint32_t k2 = k0 ^ k1 ^ 0x1BD11BDAu;
    uint32_t x0 = 0u + k0, x1 = idx + k1;
#define TFR(r) { x0 += x1; x1 = rotl32(x1, r); x1 ^= x0; }
    TFR(13) TFR(15) TFR(26) TFR(6)   x0 += k1; x1 += k2 + 1u;
    TFR(17) TFR(29) TFR(16) TFR(24)  x0 += k2; x1 += k0 + 2u;
    TFR(13) TFR(15) TFR(26) TFR(6)   x0 += k0; x1 += k1 + 3u;
    TFR(17) TFR(29) TFR(16) TFR(24)  x0 += k1; x1 += k2 + 4u;
    TFR(13) TFR(15) TFR(26) TFR(6)   x0 += k2; x1 += k0 + 5u;
#undef TFR
    return x0 ^ x1;
}
__device__ __forceinline__ float erfinv_xla(float x) {
    float w = -__logf(fmaf(-x, x, 1.0f));   // log1p(-x^2), 1-x^2 exact via fma
    float p;
    if (w < 5.0f) {
        w -= 2.5f;
        p = 2.81022636e-08f;
        p = fmaf(p, w, 3.43273939e-07f);  p = fmaf(p, w, -3.5233877e-06f);
        p = fmaf(p, w, -4.39150654e-06f); p = fmaf(p, w, 0.00021858087f);
        p = fmaf(p, w, -0.00125372503f);  p = fmaf(p, w, -0.00417768164f);
        p = fmaf(p, w, 0.246640727f);     p = fmaf(p, w, 1.50140941f);
    } else {
        w = sqrtf(w) - 3.0f;
        p = -0.000200214257f;
        p = fmaf(p, w, 0.000100950558f);  p = fmaf(p, w, 0.00134934322f);
        p = fmaf(p, w, -0.00367342844f);  p = fmaf(p, w, 0.00573950773f);
        p = fmaf(p, w, -0.0076224613f);   p = fmaf(p, w, 0.00943887047f);
        p = fmaf(p, w, 1.00167406f);      p = fmaf(p, w, 2.83297682f);
    }
    return p * x;
}
__device__ __forceinline__ float noise_at(uint32_t flat) {
    uint32_t bits = threefry_bits(flat);
    float u01 = __uint_as_float((bits >> 9) | 0x3F800000u) - 1.0f;
    const float lo = -0.99999994f;
    float u = fmaxf(lo, fmaf(u01, 1.99999994f, lo));
    return 1.4142135381698608f * erfinv_xla(u);
}
__device__ __forceinline__ float fast_tanh(float x) {
    float e = __expf(2.0f * x);
    return 1.0f - __fdividef(2.0f, e + 1.0f);
}

// ------------------------------------------------------------ bf16 split ----
__device__ __forceinline__ void split2(float f0, float f1, uint32_t& hp, uint32_t& lp) {
    __nv_bfloat16 h0 = __float2bfloat16_rn(f0), h1 = __float2bfloat16_rn(f1);
    float l0 = f0 - __bfloat162float(h0), l1 = f1 - __bfloat162float(h1);
    __nv_bfloat16 g0 = __float2bfloat16_rn(l0), g1 = __float2bfloat16_rn(l1);
    hp = ((uint32_t)__bfloat16_as_ushort(h1) << 16) | __bfloat16_as_ushort(h0);
    lp = ((uint32_t)__bfloat16_as_ushort(g1) << 16) | __bfloat16_as_ushort(g0);
}

// -------------------------------------------------------------------- prep ---
__global__ void prep_kernel(const float* __restrict__ W0, const float* __restrict__ W1,
                            const float* __restrict__ W2, const float* __restrict__ W3) {
    int i0 = blockIdx.x * blockDim.x + threadIdx.x;
    int st = gridDim.x * blockDim.x;
    for (int idx = i0; idx < 128 * K1S; idx += st) {
        int n = idx / K1S, k = idx - n * K1S;
        float v = (k < 130) ? W0[n * 130 + k] : 0.f;
        __nv_bfloat16 h = __float2bfloat16_rn(v);
        g_w0img[0][idx] = h;
        g_w0img[1][idx] = __float2bfloat16_rn(v - __bfloat162float(h));
    }
    for (int L = 0; L < 3; ++L) {
        const float* W = (L == 0) ? W1 : (L == 1) ? W2 : W3;
        for (int idx = i0; idx < 128 * K2S; idx += st) {
            int n = idx / K2S, k = idx - n * K2S;
            float v = (k < 128) ? W[n * 128 + k] : 0.f;
            __nv_bfloat16 h = __float2bfloat16_rn(v);
            g_wimg[L][0][idx] = h;
            g_wimg[L][1][idx] = __float2bfloat16_rn(v - __bfloat162float(h));
        }
    }
}

// ------------------------------------------------------------------- pass1 ---
__device__ __forceinline__ float feat_val(int k, float x0, float x1, const float* sFB) {
    if (k < 2) return (k == 0) ? x0 : x1;
    if (k < 130) {
        int j = (k < 66) ? (k - 2) : (k - 66);
        float t = fmaf(x1, sFB[64 + j], x0 * sFB[j]);
        float fr = t - rintf(t);
        return (k < 66) ? sinpif(2.0f * fr) : cospif(2.0f * fr);
    }
    return 0.f;
}

__global__ void __launch_bounds__(TPB, 1)
pass1_kernel(const float* __restrict__ X, const float* __restrict__ FB,
             const float* __restrict__ b0v) {
    double* sRed = (double*)(smem + P1_RED);
    float* sb0 = (float*)(smem + P1_B0);
    float* sFB = (float*)(smem + P1_FB);
    const uint32_t sb = smem_u32(smem);

    const int tid = threadIdx.x;
    const int w = tid >> 5, lane = tid & 31;
    const int blk = blockIdx.x;

    if (tid < 128) { sb0[tid] = b0v[tid]; sFB[tid] = FB[tid]; }
    // stage W0 hi/lo images (contiguous 77824 B)
    {
        const float4* src = (const float4*)g_w0img;
        float4* dst = (float4*)(smem + P1_W);
        for (int i = tid; i < 77824 / 16; i += TPB) dst[i] = src[i];
    }
    // build feats A hi/lo: row = tid>>1, this thread covers 36 col-pairs
    {
        int row = tid >> 1, hf = tid & 1;
        long rowg = (long)blk * 128 + row;
        float x0 = 0.f, x1 = 0.f;
        if (rowg < NPOINTS) { float2 xv = ((const float2*)X)[rowg]; x0 = xv.x; x1 = xv.y; }
        uint32_t* aHi = (uint32_t*)(smem + P1_A);
        uint32_t* aLo = aHi + 38912 / 4;
        int cp0 = hf * 36;
#pragma unroll 4
        for (int cp = cp0; cp < cp0 + 36; ++cp) {
            float f0 = feat_val(2 * cp, x0, x1, sFB);
            float f1 = feat_val(2 * cp + 1, x0, x1, sFB);
            uint32_t hp, lp;
            split2(f0, f1, hp, lp);
            aHi[row * (K1S / 2) + cp] = hp;
            aLo[row * (K1S / 2) + cp] = lp;
        }
    }
    __syncthreads();

    float acc[16][4];
#pragma unroll
    for (int t = 0; t < 16; ++t)
#pragma unroll
        for (int i = 0; i < 4; ++i) acc[t][i] = 0.f;

    const uint32_t arow = sb + P1_A + (w * 16 + (lane & 15)) * (K1S * 2) + (lane >> 4) * 16;
    const uint32_t brow = sb + P1_W + (lane & 15) * (K1S * 2) + (lane >> 4) * 16;
#pragma unroll 1
    for (int kt = 0; kt < 9; ++kt) {
        uint32_t ah[4], al[4];
        ldsm_x4(arow + kt * 32, ah);
        ldsm_x4(arow + kt * 32 + 38912, al);
#pragma unroll
        for (int tp = 0; tp < 8; ++tp) {
            uint32_t bh[4], bl[4];
            uint32_t ba = brow + tp * 16 * (K1S * 2) + kt * 32;
            ldsm_x4(ba, bh);
            ldsm_x4(ba + 38912, bl);
            mma_bf16(acc[2 * tp],     ah, bh[0], bh[2]);
            mma_bf16(acc[2 * tp + 1], ah, bh[1], bh[3]);
            mma_bf16(acc[2 * tp],     ah, bl[0], bl[2]);
            mma_bf16(acc[2 * tp + 1], ah, bl[1], bl[3]);
            mma_bf16(acc[2 * tp],     al, bh[0], bh[2]);
            mma_bf16(acc[2 * tp + 1], al, bh[1], bh[3]);
        }
    }

    // epilogue: +b0, sum(y^2) masked, store y scratch
    const int gr = lane >> 2, qc = (lane & 3) * 2;
    const long r0g = (long)blk * 128 + w * 16 + gr;
    const bool v0 = r0g < NPOINTS, v1 = (r0g + 8) < NPOINTS;
    double ls = 0.0;
    float2* gy2 = (float2*)g_y;
    const size_t tb = ((size_t)(blk * 8 + w) * 16) * 2 * 32;
#pragma unroll
    for (int nt = 0; nt < 16; ++nt) {
        float c0 = acc[nt][0] + sb0[nt * 8 + qc];
        float c1 = acc[nt][1] + sb0[nt * 8 + qc + 1];
        float c2 = acc[nt][2] + sb0[nt * 8 + qc];
        float c3 = acc[nt][3] + sb0[nt * 8 + qc + 1];
        if (v0) ls += (double)c0 * c0 + (double)c1 * c1;
        if (v1) ls += (double)c2 * c2 + (double)c3 * c3;
        gy2[tb + (nt * 2 + 0) * 32 + lane] = make_float2(c0, c1);
        gy2[tb + (nt * 2 + 1) * 32 + lane] = make_float2(c2, c3);
    }
#pragma unroll
    for (int off = 16; off; off >>= 1) ls += __shfl_down_sync(0xffffffffu, ls, off);
    if (lane == 0) sRed[w] = ls;
    __syncthreads();
    if (w == 0) {
        double v = (lane < 8) ? sRed[lane] : 0.0;
#pragma unroll
        for (int off = 4; off; off >>= 1) v += __shfl_down_sync(0xffffffffu, v, off);
        if (lane == 0) g_part[blk] = v;
    }
}

// ------------------------------------------------------- deterministic sum ---
__global__ void reduce_kernel() {
    __shared__ double s[TPB];
    double v = 0.0;
    for (int i = threadIdx.x; i < NBLK; i += TPB) v += g_part[i];
    s[threadIdx.x] = v;
    __syncthreads();
    for (int o = TPB / 2; o > 0; o >>= 1) {
        if (threadIdx.x < o) s[threadIdx.x] += s[threadIdx.x + o];
        __syncthreads();
    }
    if (threadIdx.x == 0) g_sumsq = s[0];
}

// ------------------------------------------------------------------- pass2 ---
__global__ void __launch_bounds__(TPB, 1)
pass2_kernel(const float* __restrict__ b1, const float* __restrict__ b2,
             const float* __restrict__ b3, const float* __restrict__ W4,
             const float* __restrict__ b4, float* __restrict__ out) {
    float* sBias = (float*)(smem + P2_BIAS);
    float* sW4 = (float*)(smem + P2_W4);
    float* sb4 = (float*)(smem + P2_B4);
    const uint32_t sb = smem_u32(smem);

    const int tid = threadIdx.x;
    const int w = tid >> 5, lane = tid & 31;
    const int gr = lane >> 2, qc = (lane & 3) * 2;
    const int blk = blockIdx.x;

    if (tid < 128) { sBias[tid] = b1[tid]; sBias[128 + tid] = b2[tid]; sBias[256 + tid] = b3[tid]; }
    sW4[tid] = W4[tid];
    if (tid < 2) sb4[tid] = b4[tid];

    double ss = g_sumsq;
    float power = (float)(ss * (1.0 / 128000000.0));
    float stdv = 0.0f;
    if (isfinite(power) && power > 1.1920929e-07f) stdv = sqrtf(power * 1e-3f);

    // build A = tanh(y + stdv*noise) hi/lo from scratch (accumulator ownership)
    {
        uint32_t* aHi = (uint32_t*)(smem + P2_A);
        uint32_t* aLo = aHi + 34816 / 4;
        const float2* gy2 = (const float2*)g_y;
        const size_t tb = ((size_t)(blk * 8 + w) * 16) * 2 * 32;
#pragma unroll 2
        for (int nt = 0; nt < 16; ++nt) {
#pragma unroll
            for (int h = 0; h < 2; ++h) {
                float2 y = gy2[tb + (nt * 2 + h) * 32 + lane];
                int row = w * 16 + gr + 8 * h;
                uint32_t fb = (uint32_t)(blk * 128 + row) * 128u + nt * 8 + qc;
                float v0 = fast_tanh(fmaf(noise_at(fb), stdv, y.x));
                float v1 = fast_tanh(fmaf(noise_at(fb + 1), stdv, y.y));
                uint32_t hp, lp;
                split2(v0, v1, hp, lp);
                aHi[row * (K2S / 2) + nt * 4 + (lane & 3)] = hp;
                aLo[row * (K2S / 2) + nt * 4 + (lane & 3)] = lp;
            }
        }
    }
    __syncthreads();

    const uint32_t arow = sb + P2_A + (w * 16 + (lane & 15)) * (K2S * 2) + (lane >> 4) * 16;
    const uint32_t brow = sb + P2_W + (lane & 15) * (K2S * 2) + (lane >> 4) * 16;
    float acc[16][4];

#pragma unroll 1
    for (int L = 0; L < 3; ++L) {
        // stage W(L) hi/lo (contiguous 69632 B)
        {
            const float4* src = (const float4*)g_wimg[L];
            float4* dst = (float4*)(smem + P2_W);
            for (int i = tid; i < 69632 / 16; i += TPB) dst[i] = src[i];
        }
        __syncthreads();

#pragma unroll
        for (int t = 0; t < 16; ++t)
#pragma unroll
            for (int i = 0; i < 4; ++i) acc[t][i] = 0.f;

#pragma unroll 1
        for (int kt = 0; kt < 8; ++kt) {
            uint32_t ah[4], al[4];
            ldsm_x4(arow + kt * 32, ah);
            ldsm_x4(arow + kt * 32 + 34816, al);
#pragma unroll
            for (int tp = 0; tp < 8; ++tp) {
                uint32_t bh[4], bl[4];
                uint32_t ba = brow + tp * 16 * (K2S * 2) + kt * 32;
                ldsm_x4(ba, bh);
                ldsm_x4(ba + 34816, bl);
                mma_bf16(acc[2 * tp],     ah, bh[0], bh[2]);
                mma_bf16(acc[2 * tp + 1], ah, bh[1], bh[3]);
                mma_bf16(acc[2 * tp],     ah, bl[0], bl[2]);
                mma_bf16(acc[2 * tp + 1], ah, bl[1], bl[3]);
                mma_bf16(acc[2 * tp],     al, bh[0], bh[2]);
                mma_bf16(acc[2 * tp + 1], al, bh[1], bh[3]);
            }
        }
        __syncthreads();   // all A reads done before epilogue rewrites A

        if (L < 2) {
            uint32_t* aHi = (uint32_t*)(smem + P2_A);
            uint32_t* aLo = aHi + 34816 / 4;
#pragma unroll
            for (int nt = 0; nt < 16; ++nt) {
#pragma unroll
                for (int h = 0; h < 2; ++h) {
                    float v0 = fast_tanh(acc[nt][2 * h]     + sBias[L * 128 + nt * 8 + qc]);
                    float v1 = fast_tanh(acc[nt][2 * h + 1] + sBias[L * 128 + nt * 8 + qc + 1]);
                    uint32_t hp, lp;
                    split2(v0, v1, hp, lp);
                    int row = w * 16 + gr + 8 * h;
                    aHi[row * (K2S / 2) + nt * 4 + (lane & 3)] = hp;
                    aLo[row * (K2S / 2) + nt * 4 + (lane & 3)] = lp;
                }
            }
        }
    }

    // final activations + output layer, fully in registers
    float p00 = 0.f, p01 = 0.f, p10 = 0.f, p11 = 0.f;
#pragma unroll
    for (int nt = 0; nt < 16; ++nt) {
#pragma unroll
        for (int i = 0; i < 2; ++i) {
            int col = nt * 8 + qc + i;
            float b = sBias[256 + col];
            float h0 = fast_tanh(acc[nt][i] + b);
            float h1 = fast_tanh(acc[nt][2 + i] + b);
            float w0 = sW4[col], w1 = sW4[128 + col];
            p00 = fmaf(h0, w0, p00); p01 = fmaf(h0, w1, p01);
            p10 = fmaf(h1, w0, p10); p11 = fmaf(h1, w1, p11);
        }
    }
#pragma unroll
    for (int m = 1; m <= 2; m <<= 1) {
        p00 += __shfl_xor_sync(0xffffffffu, p00, m);
        p01 += __shfl_xor_sync(0xffffffffu, p01, m);
        p10 += __shfl_xor_sync(0xffffffffu, p10, m);
        p11 += __shfl_xor_sync(0xffffffffu, p11, m);
    }
    if ((lane & 3) == 0) {
        long r0g = (long)blk * 128 + w * 16 + gr;
        if (r0g < NPOINTS)
            ((float2*)out)[r0g] = make_float2(p00 + sb4[0], p01 + sb4[1]);
        if (r0g + 8 < NPOINTS)
            ((float2*)out)[r0g + 8] = make_float2(p10 + sb4[0], p11 + sb4[1]);
    }
}

// ------------------------------------------------------------------- host ----
extern "C" void kernel_launch(void* const* d_in, const int* in_sizes, int n_in,
                              void* d_out, int out_size) {
    const float* X  = (const float*)d_in[0];
    const float* FB = (const float*)d_in[1];
    const float* W0 = (const float*)d_in[2];
    const float* b0 = (const float*)d_in[3];
    const float* W1 = (const float*)d_in[4];
    const float* b1 = (const float*)d_in[5];
    const float* W2 = (const float*)d_in[6];
    const float* b2 = (const float*)d_in[7];
    const float* W3 = (const float*)d_in[8];
    const float* b3 = (const float*)d_in[9];
    const float* W4 = (const float*)d_in[10];
    const float* b4 = (const float*)d_in[11];
    float* out = (float*)d_out;

    cudaFuncSetAttribute(pass1_kernel, cudaFuncAttributeMaxDynamicSharedMemorySize, P1_SMEM);
    cudaFuncSetAttribute(pass2_kernel, cudaFuncAttributeMaxDynamicSharedMemorySize, P2_SMEM);

    prep_kernel<<<64, TPB>>>(W0, W1, W2, W3);
    pass1_kernel<<<NBLK, TPB, P1_SMEM>>>(X, FB, b0);
    reduce_kernel<<<1, TPB>>>();
    pass2_kernel<<<NBLK, TPB, P2_SMEM>>>(b1, b2, b3, W4, b4, out);
}

// round 7
// speedup vs baseline: 2.0075x; 1.2505x over previous
#include <cuda_runtime.h>
#include <cuda_bf16.h>
#include <cstdint>
#include <math.h>

// ----------------------------------------------------------------------------
// SimplePINN forward on GB300 (base sm_103) — HMMA bf16 split-2, 3-pass.
// R7: back to the R4-verified SMEM weight path; occupancy via ONE 512-thread
//     CTA (16 warps) per 128-row tile, warp pairs split N (cols 0-63 / 64-127).
// ----------------------------------------------------------------------------

#define NPOINTS 1000000
#define NBLK    7813          // ceil(1e6/128)
#define TPB     512

#define K1S 152               // pass1 A/W row stride in bf16 (K=144 pad)
#define K2S 136               // pass2 A/W row stride in bf16 (K=128 pad)

// pass1 smem layout (bytes)
#define P1_RED  0             // 16 doubles
#define P1_B0   128
#define P1_FB   640
#define P1_A    1152          // A_hi (38912) then A_lo (38912)
#define P1_W    78976         // W_hi (38912) then W_lo (38912)
#define P1_SMEM 156800
// pass2 smem layout
#define P2_BIAS 0             // 384 f
#define P2_W4   1536          // 256 f
#define P2_B4   2560          // 2 f
#define P2_A    2688          // A_hi (34816) then A_lo (34816)
#define P2_W    72320         // W_hi (34816) then W_lo (34816)
#define P2_EXCH 141952        // 512 f
#define P2_SMEM 144000

__device__ __align__(16) __nv_bfloat16 g_w0img[2][128 * K1S];
__device__ __align__(16) __nv_bfloat16 g_wimg[3][2][128 * K2S];
__device__ float  g_y[(size_t)NBLK * 16384];
__device__ double g_part[NBLK];
__device__ double g_sumsq;

extern __shared__ __align__(16) char smem[];

// ------------------------------------------------------------ ptx helpers ---
__device__ __forceinline__ uint32_t smem_u32(const void* p) {
    uint32_t a;
    asm("{ .reg .u64 t; cvta.to.shared.u64 t, %1; cvt.u32.u64 %0, t; }" : "=r"(a) : "l"(p));
    return a;
}
__device__ __forceinline__ void ldsm_x4(uint32_t addr, uint32_t r[4]) {
    asm volatile("ldmatrix.sync.aligned.m8n8.x4.shared.b16 {%0,%1,%2,%3}, [%4];"
                 : "=r"(r[0]), "=r"(r[1]), "=r"(r[2]), "=r"(r[3]) : "r"(addr));
}
__device__ __forceinline__ void mma_bf16(float* c, const uint32_t* a, uint32_t b0, uint32_t b1) {
    asm volatile("mma.sync.aligned.m16n8k16.row.col.f32.bf16.bf16.f32 "
                 "{%0,%1,%2,%3}, {%4,%5,%6,%7}, {%8,%9}, {%0,%1,%2,%3};"
                 : "+f"(c[0]), "+f"(c[1]), "+f"(c[2]), "+f"(c[3])
                 : "r"(a[0]), "r"(a[1]), "r"(a[2]), "r"(a[3]), "r"(b0), "r"(b1));
}

// ---------------------------------------------------------------- threefry ---
__device__ __forceinline__ uint32_t rotl32(uint32_t x, int r) { return __funnelshift_l(x, x, r); }
__device__ __forceinline__ uint32_t threefry_bits(uint32_t idx) {
    const uint32_t k0 = 0u, k1 = 42u;
    const uint32_t k2 = k0 ^ k1 ^ 0x1BD11BDAu;
    uint32_t x0 = 0u + k0, x1 = idx + k1;
#define TFR(r) { x0 += x1; x1 = rotl32(x1, r); x1 ^= x0; }
    TFR(13) TFR(15) TFR(26) TFR(6)   x0 += k1; x1 += k2 + 1u;
    TFR(17) TFR(29) TFR(16) TFR(24)  x0 += k2; x1 += k0 + 2u;
    TFR(13) TFR(15) TFR(26) TFR(6)   x0 += k0; x1 += k1 + 3u;
    TFR(17) TFR(29) TFR(16) TFR(24)  x0 += k1; x1 += k2 + 4u;
    TFR(13) TFR(15) TFR(26) TFR(6)   x0 += k2; x1 += k0 + 5u;
#undef TFR
    return x0 ^ x1;
}
__device__ __forceinline__ float erfinv_xla(float x) {
    float w = -__logf(fmaf(-x, x, 1.0f));
    float p;
    if (w < 5.0f) {
        w -= 2.5f;
        p = 2.81022636e-08f;
        p = fmaf(p, w, 3.43273939e-07f);  p = fmaf(p, w, -3.5233877e-06f);
        p = fmaf(p, w, -4.39150654e-06f); p = fmaf(p, w, 0.00021858087f);
        p = fmaf(p, w, -0.00125372503f);  p = fmaf(p, w, -0.00417768164f);
        p = fmaf(p, w, 0.246640727f);     p = fmaf(p, w, 1.50140941f);
    } else {
        w = sqrtf(w) - 3.0f;
        p = -0.000200214257f;
        p = fmaf(p, w, 0.000100950558f);  p = fmaf(p, w, 0.00134934322f);
        p = fmaf(p, w, -0.00367342844f);  p = fmaf(p, w, 0.00573950773f);
        p = fmaf(p, w, -0.0076224613f);   p = fmaf(p, w, 0.00943887047f);
        p = fmaf(p, w, 1.00167406f);      p = fmaf(p, w, 2.83297682f);
    }
    return p * x;
}
__device__ __forceinline__ float noise_at(uint32_t flat) {
    uint32_t bits = threefry_bits(flat);
    float u01 = __uint_as_float((bits >> 9) | 0x3F800000u) - 1.0f;
    const float lo = -0.99999994f;
    float u = fmaxf(lo, fmaf(u01, 1.99999994f, lo));
    return 1.4142135381698608f * erfinv_xla(u);
}
__device__ __forceinline__ float fast_tanh(float x) {
    float e = __expf(2.0f * x);
    return 1.0f - __fdividef(2.0f, e + 1.0f);
}

// ------------------------------------------------------------ bf16 split ----
__device__ __forceinline__ void split2(float f0, float f1, uint32_t& hp, uint32_t& lp) {
    __nv_bfloat16 h0 = __float2bfloat16_rn(f0), h1 = __float2bfloat16_rn(f1);
    float l0 = f0 - __bfloat162float(h0), l1 = f1 - __bfloat162float(h1);
    __nv_bfloat16 g0 = __float2bfloat16_rn(l0), g1 = __float2bfloat16_rn(l1);
    hp = ((uint32_t)__bfloat16_as_ushort(h1) << 16) | __bfloat16_as_ushort(h0);
    lp = ((uint32_t)__bfloat16_as_ushort(g1) << 16) | __bfloat16_as_ushort(g0);
}

// -------------------------------------------------------------------- prep ---
__global__ void prep_img_kernel(const float* __restrict__ W0, const float* __restrict__ W1,
                                const float* __restrict__ W2, const float* __restrict__ W3) {
    int i0 = blockIdx.x * blockDim.x + threadIdx.x;
    int st = gridDim.x * blockDim.x;
    for (int idx = i0; idx < 128 * K1S; idx += st) {
        int n = idx / K1S, k = idx - n * K1S;
        float v = (k < 130) ? W0[n * 130 + k] : 0.f;
        __nv_bfloat16 h = __float2bfloat16_rn(v);
        g_w0img[0][idx] = h;
        g_w0img[1][idx] = __float2bfloat16_rn(v - __bfloat162float(h));
    }
    for (int L = 0; L < 3; ++L) {
        const float* W = (L == 0) ? W1 : (L == 1) ? W2 : W3;
        for (int idx = i0; idx < 128 * K2S; idx += st) {
            int n = idx / K2S, k = idx - n * K2S;
            float v = (k < 128) ? W[n * 128 + k] : 0.f;
            __nv_bfloat16 h = __float2bfloat16_rn(v);
            g_wimg[L][0][idx] = h;
            g_wimg[L][1][idx] = __float2bfloat16_rn(v - __bfloat162float(h));
        }
    }
}

// ------------------------------------------------------------------- pass1 ---
__device__ __forceinline__ float feat_val(int k, float x0, float x1, const float* sFB) {
    if (k < 2) return (k == 0) ? x0 : x1;
    if (k < 130) {
        int j = (k < 66) ? (k - 2) : (k - 66);
        float t = fmaf(x1, sFB[64 + j], x0 * sFB[j]);
        float fr = t - rintf(t);
        return (k < 66) ? sinpif(2.0f * fr) : cospif(2.0f * fr);
    }
    return 0.f;
}

__global__ void __launch_bounds__(TPB, 1)
pass1_kernel(const float* __restrict__ X, const float* __restrict__ FB,
             const float* __restrict__ b0v) {
    double* sRed = (double*)(smem + P1_RED);
    float* sb0 = (float*)(smem + P1_B0);
    float* sFB = (float*)(smem + P1_FB);
    const uint32_t sb = smem_u32(smem);

    const int tid = threadIdx.x;
    const int w = tid >> 5, lane = tid & 31;
    const int rg = w >> 1, nh = w & 1;          // row-group 0..7, n-half 0..1
    const int blk = blockIdx.x;

    if (tid < 128) { sb0[tid] = b0v[tid]; sFB[tid] = FB[tid]; }
    // stage W0 hi/lo (77824 B)
    {
        const float4* src = (const float4*)g_w0img;
        float4* dst = (float4*)(smem + P1_W);
        for (int i = tid; i < 77824 / 16; i += TPB) dst[i] = src[i];
    }
    // build feats A hi/lo (4 threads per row, 18 col-pairs each)
    {
        int row = tid >> 2, q = tid & 3;
        long rowg = (long)blk * 128 + row;
        float x0 = 0.f, x1 = 0.f;
        if (rowg < NPOINTS) { float2 xv = ((const float2*)X)[rowg]; x0 = xv.x; x1 = xv.y; }
        uint32_t* aHi = (uint32_t*)(smem + P1_A);
        uint32_t* aLo = aHi + 38912 / 4;
        int cp0 = q * 18;
#pragma unroll 6
        for (int cp = cp0; cp < cp0 + 18; ++cp) {
            float f0 = feat_val(2 * cp, x0, x1, sFB);
            float f1 = feat_val(2 * cp + 1, x0, x1, sFB);
            uint32_t hp, lp;
            split2(f0, f1, hp, lp);
            aHi[row * (K1S / 2) + cp] = hp;
            aLo[row * (K1S / 2) + cp] = lp;
        }
    }
    __syncthreads();

    float acc[8][4];
#pragma unroll
    for (int t = 0; t < 8; ++t)
#pragma unroll
        for (int i = 0; i < 4; ++i) acc[t][i] = 0.f;

    const uint32_t arow = sb + P1_A + (rg * 16 + (lane & 15)) * (K1S * 2) + (lane >> 4) * 16;
    const uint32_t brow = sb + P1_W + (lane & 15) * (K1S * 2) + (lane >> 4) * 16;
#pragma unroll 1
    for (int kt = 0; kt < 9; ++kt) {
        uint32_t ah[4], al[4];
        ldsm_x4(arow + kt * 32, ah);
        ldsm_x4(arow + kt * 32 + 38912, al);
#pragma unroll
        for (int tpl = 0; tpl < 4; ++tpl) {
            int tp = nh * 4 + tpl;
            uint32_t bh[4], bl[4];
            uint32_t ba = brow + tp * 16 * (K1S * 2) + kt * 32;
            ldsm_x4(ba, bh);
            ldsm_x4(ba + 38912, bl);
            mma_bf16(acc[2 * tpl],     ah, bh[0], bh[2]);
            mma_bf16(acc[2 * tpl + 1], ah, bh[1], bh[3]);
            mma_bf16(acc[2 * tpl],     ah, bl[0], bl[2]);
            mma_bf16(acc[2 * tpl + 1], ah, bl[1], bl[3]);
            mma_bf16(acc[2 * tpl],     al, bh[0], bh[2]);
            mma_bf16(acc[2 * tpl + 1], al, bh[1], bh[3]);
        }
    }

    // epilogue: +b0, masked sum(y^2), store y scratch
    const int gr = lane >> 2, qc = (lane & 3) * 2;
    const long r0g = (long)blk * 128 + rg * 16 + gr;
    const bool v0 = r0g < NPOINTS, v1 = (r0g + 8) < NPOINTS;
    double ls = 0.0;
    float2* gy2 = (float2*)g_y;
    const size_t tb = ((size_t)(blk * 16 + w)) * 8 * 64;
#pragma unroll
    for (int nt = 0; nt < 8; ++nt) {
        int colg = (nh * 8 + nt) * 8 + qc;
        float c0 = acc[nt][0] + sb0[colg];
        float c1 = acc[nt][1] + sb0[colg + 1];
        float c2 = acc[nt][2] + sb0[colg];
        float c3 = acc[nt][3] + sb0[colg + 1];
        if (v0) ls += (double)c0 * c0 + (double)c1 * c1;
        if (v1) ls += (double)c2 * c2 + (double)c3 * c3;
        gy2[tb + nt * 64 + lane]      = make_float2(c0, c1);
        gy2[tb + nt * 64 + 32 + lane] = make_float2(c2, c3);
    }
#pragma unroll
    for (int off = 16; off; off >>= 1) ls += __shfl_down_sync(0xffffffffu, ls, off);
    if (lane == 0) sRed[w] = ls;
    __syncthreads();
    if (w == 0) {
        double v = (lane < 16) ? sRed[lane] : 0.0;
#pragma unroll
        for (int off = 8; off; off >>= 1) v += __shfl_down_sync(0xffffffffu, v, off);
        if (lane == 0) g_part[blk] = v;
    }
}

// ------------------------------------------------------- deterministic sum ---
__global__ void reduce_kernel() {
    __shared__ double s[256];
    double v = 0.0;
    for (int i = threadIdx.x; i < NBLK; i += 256) v += g_part[i];
    s[threadIdx.x] = v;
    __syncthreads();
    for (int o = 128; o > 0; o >>= 1) {
        if (threadIdx.x < o) s[threadIdx.x] += s[threadIdx.x + o];
        __syncthreads();
    }
    if (threadIdx.x == 0) g_sumsq = s[0];
}

// ------------------------------------------------------------------- pass2 ---
__global__ void __launch_bounds__(TPB, 1)
pass2_kernel(const float* __restrict__ b1, const float* __restrict__ b2,
             const float* __restrict__ b3, const float* __restrict__ W4,
             const float* __restrict__ b4, float* __restrict__ out) {
    float* sBias = (float*)(smem + P2_BIAS);
    float* sW4 = (float*)(smem + P2_W4);
    float* sb4 = (float*)(smem + P2_B4);
    float* exch = (float*)(smem + P2_EXCH);
    const uint32_t sb = smem_u32(smem);

    const int tid = threadIdx.x;
    const int w = tid >> 5, lane = tid & 31;
    const int rg = w >> 1, nh = w & 1;
    const int gr = lane >> 2, qc = (lane & 3) * 2;
    const int blk = blockIdx.x;

    if (tid < 128) { sBias[tid] = b1[tid]; sBias[128 + tid] = b2[tid]; sBias[256 + tid] = b3[tid]; }
    if (tid < 256) sW4[tid] = W4[tid];
    if (tid < 2) sb4[tid] = b4[tid];

    double ss = g_sumsq;
    float power = (float)(ss * (1.0 / 128000000.0));
    float stdv = 0.0f;
    if (isfinite(power) && power > 1.1920929e-07f) stdv = sqrtf(power * 1e-3f);

    // build A = tanh(y + stdv*noise) hi/lo (warp owns rows rg*16.., cols nh*64..)
    {
        uint32_t* aHi = (uint32_t*)(smem + P2_A);
        uint32_t* aLo = aHi + 34816 / 4;
        const float2* gy2 = (const float2*)g_y;
        const size_t tb = ((size_t)(blk * 16 + w)) * 8 * 64;
#pragma unroll 2
        for (int nt = 0; nt < 8; ++nt) {
#pragma unroll
            for (int h = 0; h < 2; ++h) {
                float2 y = gy2[tb + nt * 64 + h * 32 + lane];
                int row = rg * 16 + gr + 8 * h;
                int col = (nh * 8 + nt) * 8 + qc;
                uint32_t fb = (uint32_t)(blk * 128 + row) * 128u + col;
                float v0 = fast_tanh(fmaf(noise_at(fb), stdv, y.x));
                float v1 = fast_tanh(fmaf(noise_at(fb + 1), stdv, y.y));
                uint32_t hp, lp;
                split2(v0, v1, hp, lp);
                aHi[row * (K2S / 2) + (nh * 8 + nt) * 4 + (lane & 3)] = hp;
                aLo[row * (K2S / 2) + (nh * 8 + nt) * 4 + (lane & 3)] = lp;
            }
        }
    }

    const uint32_t arow = sb + P2_A + (rg * 16 + (lane & 15)) * (K2S * 2) + (lane >> 4) * 16;
    const uint32_t brow = sb + P2_W + (lane & 15) * (K2S * 2) + (lane >> 4) * 16;
    float acc[8][4];

#pragma unroll 1
    for (int L = 0; L < 3; ++L) {
        // stage W(L) hi/lo (69632 B); also orders prior A writes before mma reads
        {
            const float4* src = (const float4*)g_wimg[L];
            float4* dst = (float4*)(smem + P2_W);
            for (int i = tid; i < 69632 / 16; i += TPB) dst[i] = src[i];
        }
        __syncthreads();

#pragma unroll
        for (int t = 0; t < 8; ++t)
#pragma unroll
            for (int i = 0; i < 4; ++i) acc[t][i] = 0.f;

#pragma unroll 1
        for (int kt = 0; kt < 8; ++kt) {
            uint32_t ah[4], al[4];
            ldsm_x4(arow + kt * 32, ah);
            ldsm_x4(arow + kt * 32 + 34816, al);
#pragma unroll
            for (int tpl = 0; tpl < 4; ++tpl) {
                int tp = nh * 4 + tpl;
                uint32_t bh[4], bl[4];
                uint32_t ba = brow + tp * 16 * (K2S * 2) + kt * 32;
                ldsm_x4(ba, bh);
                ldsm_x4(ba + 34816, bl);
                mma_bf16(acc[2 * tpl],     ah, bh[0], bh[2]);
                mma_bf16(acc[2 * tpl + 1], ah, bh[1], bh[3]);
                mma_bf16(acc[2 * tpl],     ah, bl[0], bl[2]);
                mma_bf16(acc[2 * tpl + 1], ah, bl[1], bl[3]);
                mma_bf16(acc[2 * tpl],     al, bh[0], bh[2]);
                mma_bf16(acc[2 * tpl + 1], al, bh[1], bh[3]);
            }
        }
        __syncthreads();   // all A/W reads done before A rewrite / next staging

        if (L < 2) {
            uint32_t* aHi = (uint32_t*)(smem + P2_A);
            uint32_t* aLo = aHi + 34816 / 4;
#pragma unroll
            for (int nt = 0; nt < 8; ++nt) {
                int colg = (nh * 8 + nt) * 8 + qc;
#pragma unroll
                for (int h = 0; h < 2; ++h) {
                    float v0 = fast_tanh(acc[nt][2 * h]     + sBias[L * 128 + colg]);
                    float v1 = fast_tanh(acc[nt][2 * h + 1] + sBias[L * 128 + colg + 1]);
                    uint32_t hp, lp;
                    split2(v0, v1, hp, lp);
                    int row = rg * 16 + gr + 8 * h;
                    aHi[row * (K2S / 2) + (nh * 8 + nt) * 4 + (lane & 3)] = hp;
                    aLo[row * (K2S / 2) + (nh * 8 + nt) * 4 + (lane & 3)] = lp;
                }
            }
        }
    }

    // final activations + output partials over this warp's 64 cols
    float p00 = 0.f, p01 = 0.f, p10 = 0.f, p11 = 0.f;
#pragma unroll
    for (int nt = 0; nt < 8; ++nt) {
#pragma unroll
        for (int i = 0; i < 2; ++i) {
            int col = (nh * 8 + nt) * 8 + qc + i;
            float b = sBias[256 + col];
            float h0 = fast_tanh(acc[nt][i] + b);
            float h1 = fast_tanh(acc[nt][2 + i] + b);
            float w0 = sW4[col], w1 = sW4[128 + col];
            p00 = fmaf(h0, w0, p00); p01 = fmaf(h0, w1, p01);
            p10 = fmaf(h1, w0, p10); p11 = fmaf(h1, w1, p11);
        }
    }
#pragma unroll
    for (int m = 1; m <= 2; m <<= 1) {
        p00 += __shfl_xor_sync(0xffffffffu, p00, m);
        p01 += __shfl_xor_sync(0xffffffffu, p01, m);
        p10 += __shfl_xor_sync(0xffffffffu, p10, m);
        p11 += __shfl_xor_sync(0xffffffffu, p11, m);
    }
    if ((lane & 3) == 0) {
        int row0 = rg * 16 + gr;
        exch[(row0 * 2 + nh) * 2 + 0] = p00;
        exch[(row0 * 2 + nh) * 2 + 1] = p01;
        exch[((row0 + 8) * 2 + nh) * 2 + 0] = p10;
        exch[((row0 + 8) * 2 + nh) * 2 + 1] = p11;
    }
    __syncthreads();
    if (tid < 256) {
        int row = tid >> 1, o = tid & 1;
        long rowg = (long)blk * 128 + row;
        if (rowg < NPOINTS)
            out[rowg * 2 + o] = exch[(row * 2 + 0) * 2 + o] + exch[(row * 2 + 1) * 2 + o] + sb4[o];
    }
}

// ------------------------------------------------------------------- host ----
extern "C" void kernel_launch(void* const* d_in, const int* in_sizes, int n_in,
                              void* d_out, int out_size) {
    const float* X  = (const float*)d_in[0];
    const float* FB = (const float*)d_in[1];
    const float* W0 = (const float*)d_in[2];
    const float* b0 = (const float*)d_in[3];
    const float* W1 = (const float*)d_in[4];
    const float* b1 = (const float*)d_in[5];
    const float* W2 = (const float*)d_in[6];
    const float* b2 = (const float*)d_in[7];
    const float* W3 = (const float*)d_in[8];
    const float* b3 = (const float*)d_in[9];
    const float* W4 = (const float*)d_in[10];
    const float* b4 = (const float*)d_in[11];
    float* out = (float*)d_out;

    cudaFuncSetAttribute(pass1_kernel, cudaFuncAttributeMaxDynamicSharedMemorySize, P1_SMEM);
    cudaFuncSetAttribute(pass2_kernel, cudaFuncAttributeMaxDynamicSharedMemorySize, P2_SMEM);

    prep_img_kernel<<<64, 256>>>(W0, W1, W2, W3);
    pass1_kernel<<<NBLK, TPB, P1_SMEM>>>(X, FB, b0);
    reduce_kernel<<<1, 256>>>();
    pass2_kernel<<<NBLK, TPB, P2_SMEM>>>(b1, b2, b3, W4, b4, out);
}

// round 8
// speedup vs baseline: 2.3103x; 1.1509x over previous
#include <cuda_runtime.h>
#include <cuda_bf16.h>
#include <cstdint>
#include <math.h>

// ----------------------------------------------------------------------------
// SimplePINN forward on GB300 (base sm_103) — HMMA bf16 split-2, 3-pass.
// R8: noise (threefry+erfinv) moved to pass1 epilogue, stored bf16x2 in a
//     256MB scratch; pass2 just loads+fma. Removes ~0.5ms ALU from pass2.
// ----------------------------------------------------------------------------

#define NPOINTS 1000000
#define NBLK    7813          // ceil(1e6/128)
#define TPB     512

#define K1S 152               // pass1 A/W row stride in bf16 (K=144 pad)
#define K2S 136               // pass2 A/W row stride in bf16 (K=128 pad)

// pass1 smem layout (bytes)
#define P1_RED  0             // 16 doubles
#define P1_B0   128
#define P1_FB   640
#define P1_A    1152          // A_hi (38912) then A_lo (38912)
#define P1_W    78976         // W_hi (38912) then W_lo (38912)
#define P1_SMEM 156800
// pass2 smem layout
#define P2_BIAS 0             // 384 f
#define P2_W4   1536          // 256 f
#define P2_B4   2560          // 2 f
#define P2_A    2688          // A_hi (34816) then A_lo (34816)
#define P2_W    72320         // W_hi (34816) then W_lo (34816)
#define P2_EXCH 141952        // 512 f
#define P2_SMEM 144000

__device__ __align__(16) __nv_bfloat16 g_w0img[2][128 * K1S];
__device__ __align__(16) __nv_bfloat16 g_wimg[3][2][128 * K2S];
__device__ float    g_y[(size_t)NBLK * 16384];
__device__ uint32_t g_n[(size_t)NBLK * 8192];    // bf16x2-packed noise
__device__ double g_part[NBLK];
__device__ double g_sumsq;

extern __shared__ __align__(16) char smem[];

// ------------------------------------------------------------ ptx helpers ---
__device__ __forceinline__ uint32_t smem_u32(const void* p) {
    uint32_t a;
    asm("{ .reg .u64 t; cvta.to.shared.u64 t, %1; cvt.u32.u64 %0, t; }" : "=r"(a) : "l"(p));
    return a;
}
__device__ __forceinline__ void ldsm_x4(uint32_t addr, uint32_t r[4]) {
    asm volatile("ldmatrix.sync.aligned.m8n8.x4.shared.b16 {%0,%1,%2,%3}, [%4];"
                 : "=r"(r[0]), "=r"(r[1]), "=r"(r[2]), "=r"(r[3]) : "r"(addr));
}
__device__ __forceinline__ void mma_bf16(float* c, const uint32_t* a, uint32_t b0, uint32_t b1) {
    asm volatile("mma.sync.aligned.m16n8k16.row.col.f32.bf16.bf16.f32 "
                 "{%0,%1,%2,%3}, {%4,%5,%6,%7}, {%8,%9}, {%0,%1,%2,%3};"
                 : "+f"(c[0]), "+f"(c[1]), "+f"(c[2]), "+f"(c[3])
                 : "r"(a[0]), "r"(a[1]), "r"(a[2]), "r"(a[3]), "r"(b0), "r"(b1));
}

// ---------------------------------------------------------------- threefry ---
__device__ __forceinline__ uint32_t rotl32(uint32_t x, int r) { return __funnelshift_l(x, x, r); }
__device__ __forceinline__ uint32_t threefry_bits(uint32_t idx) {
    const uint32_t k0 = 0u, k1 = 42u;
    const uint32_t k2 = k0 ^ k1 ^ 0x1BD11BDAu;
    uint32_t x0 = 0u + k0, x1 = idx + k1;
#define TFR(r) { x0 += x1; x1 = rotl32(x1, r); x1 ^= x0; }
    TFR(13) TFR(15) TFR(26) TFR(6)   x0 += k1; x1 += k2 + 1u;
    TFR(17) TFR(29) TFR(16) TFR(24)  x0 += k2; x1 += k0 + 2u;
    TFR(13) TFR(15) TFR(26) TFR(6)   x0 += k0; x1 += k1 + 3u;
    TFR(17) TFR(29) TFR(16) TFR(24)  x0 += k1; x1 += k2 + 4u;
    TFR(13) TFR(15) TFR(26) TFR(6)   x0 += k2; x1 += k0 + 5u;
#undef TFR
    return x0 ^ x1;
}
__device__ __forceinline__ float erfinv_xla(float x) {
    float w = -__logf(fmaf(-x, x, 1.0f));
    float p;
    if (w < 5.0f) {
        w -= 2.5f;
        p = 2.81022636e-08f;
        p = fmaf(p, w, 3.43273939e-07f);  p = fmaf(p, w, -3.5233877e-06f);
        p = fmaf(p, w, -4.39150654e-06f); p = fmaf(p, w, 0.00021858087f);
        p = fmaf(p, w, -0.00125372503f);  p = fmaf(p, w, -0.00417768164f);
        p = fmaf(p, w, 0.246640727f);     p = fmaf(p, w, 1.50140941f);
    } else {
        w = sqrtf(w) - 3.0f;
        p = -0.000200214257f;
        p = fmaf(p, w, 0.000100950558f);  p = fmaf(p, w, 0.00134934322f);
        p = fmaf(p, w, -0.00367342844f);  p = fmaf(p, w, 0.00573950773f);
        p = fmaf(p, w, -0.0076224613f);   p = fmaf(p, w, 0.00943887047f);
        p = fmaf(p, w, 1.00167406f);      p = fmaf(p, w, 2.83297682f);
    }
    return p * x;
}
__device__ __forceinline__ float noise_at(uint32_t flat) {
    uint32_t bits = threefry_bits(flat);
    float u01 = __uint_as_float((bits >> 9) | 0x3F800000u) - 1.0f;
    const float lo = -0.99999994f;
    float u = fmaxf(lo, fmaf(u01, 1.99999994f, lo));
    return 1.4142135381698608f * erfinv_xla(u);
}
__device__ __forceinline__ float fast_tanh(float x) {
    float e = __expf(2.0f * x);
    return 1.0f - __fdividef(2.0f, e + 1.0f);
}

// ------------------------------------------------------------ bf16 split ----
__device__ __forceinline__ void split2(float f0, float f1, uint32_t& hp, uint32_t& lp) {
    __nv_bfloat16 h0 = __float2bfloat16_rn(f0), h1 = __float2bfloat16_rn(f1);
    float l0 = f0 - __bfloat162float(h0), l1 = f1 - __bfloat162float(h1);
    __nv_bfloat16 g0 = __float2bfloat16_rn(l0), g1 = __float2bfloat16_rn(l1);
    hp = ((uint32_t)__bfloat16_as_ushort(h1) << 16) | __bfloat16_as_ushort(h0);
    lp = ((uint32_t)__bfloat16_as_ushort(g1) << 16) | __bfloat16_as_ushort(g0);
}
__device__ __forceinline__ uint32_t packbf2(float f0, float f1) {
    __nv_bfloat16 h0 = __float2bfloat16_rn(f0), h1 = __float2bfloat16_rn(f1);
    return ((uint32_t)__bfloat16_as_ushort(h1) << 16) | __bfloat16_as_ushort(h0);
}

// -------------------------------------------------------------------- prep ---
__global__ void prep_img_kernel(const float* __restrict__ W0, const float* __restrict__ W1,
                                const float* __restrict__ W2, const float* __restrict__ W3) {
    int i0 = blockIdx.x * blockDim.x + threadIdx.x;
    int st = gridDim.x * blockDim.x;
    for (int idx = i0; idx < 128 * K1S; idx += st) {
        int n = idx / K1S, k = idx - n * K1S;
        float v = (k < 130) ? W0[n * 130 + k] : 0.f;
        __nv_bfloat16 h = __float2bfloat16_rn(v);
        g_w0img[0][idx] = h;
        g_w0img[1][idx] = __float2bfloat16_rn(v - __bfloat162float(h));
    }
    for (int L = 0; L < 3; ++L) {
        const float* W = (L == 0) ? W1 : (L == 1) ? W2 : W3;
        for (int idx = i0; idx < 128 * K2S; idx += st) {
            int n = idx / K2S, k = idx - n * K2S;
            float v = (k < 128) ? W[n * 128 + k] : 0.f;
            __nv_bfloat16 h = __float2bfloat16_rn(v);
            g_wimg[L][0][idx] = h;
            g_wimg[L][1][idx] = __float2bfloat16_rn(v - __bfloat162float(h));
        }
    }
}

// ------------------------------------------------------------------- pass1 ---
__device__ __forceinline__ float feat_val(int k, float x0, float x1, const float* sFB) {
    if (k < 2) return (k == 0) ? x0 : x1;
    if (k < 130) {
        int j = (k < 66) ? (k - 2) : (k - 66);
        float t = fmaf(x1, sFB[64 + j], x0 * sFB[j]);
        float fr = t - rintf(t);
        return (k < 66) ? sinpif(2.0f * fr) : cospif(2.0f * fr);
    }
    return 0.f;
}

__global__ void __launch_bounds__(TPB, 1)
pass1_kernel(const float* __restrict__ X, const float* __restrict__ FB,
             const float* __restrict__ b0v) {
    double* sRed = (double*)(smem + P1_RED);
    float* sb0 = (float*)(smem + P1_B0);
    float* sFB = (float*)(smem + P1_FB);
    const uint32_t sb = smem_u32(smem);

    const int tid = threadIdx.x;
    const int w = tid >> 5, lane = tid & 31;
    const int rg = w >> 1, nh = w & 1;          // row-group 0..7, n-half 0..1
    const int blk = blockIdx.x;

    if (tid < 128) { sb0[tid] = b0v[tid]; sFB[tid] = FB[tid]; }
    // stage W0 hi/lo (77824 B)
    {
        const float4* src = (const float4*)g_w0img;
        float4* dst = (float4*)(smem + P1_W);
        for (int i = tid; i < 77824 / 16; i += TPB) dst[i] = src[i];
    }
    // build feats A hi/lo (4 threads per row, 18 col-pairs each)
    {
        int row = tid >> 2, q = tid & 3;
        long rowg = (long)blk * 128 + row;
        float x0 = 0.f, x1 = 0.f;
        if (rowg < NPOINTS) { float2 xv = ((const float2*)X)[rowg]; x0 = xv.x; x1 = xv.y; }
        uint32_t* aHi = (uint32_t*)(smem + P1_A);
        uint32_t* aLo = aHi + 38912 / 4;
        int cp0 = q * 18;
#pragma unroll 6
        for (int cp = cp0; cp < cp0 + 18; ++cp) {
            float f0 = feat_val(2 * cp, x0, x1, sFB);
            float f1 = feat_val(2 * cp + 1, x0, x1, sFB);
            uint32_t hp, lp;
            split2(f0, f1, hp, lp);
            aHi[row * (K1S / 2) + cp] = hp;
            aLo[row * (K1S / 2) + cp] = lp;
        }
    }
    __syncthreads();

    float acc[8][4];
#pragma unroll
    for (int t = 0; t < 8; ++t)
#pragma unroll
        for (int i = 0; i < 4; ++i) acc[t][i] = 0.f;

    const uint32_t arow = sb + P1_A + (rg * 16 + (lane & 15)) * (K1S * 2) + (lane >> 4) * 16;
    const uint32_t brow = sb + P1_W + (lane & 15) * (K1S * 2) + (lane >> 4) * 16;
#pragma unroll 1
    for (int kt = 0; kt < 9; ++kt) {
        uint32_t ah[4], al[4];
        ldsm_x4(arow + kt * 32, ah);
        ldsm_x4(arow + kt * 32 + 38912, al);
#pragma unroll
        for (int tpl = 0; tpl < 4; ++tpl) {
            int tp = nh * 4 + tpl;
            uint32_t bh[4], bl[4];
            uint32_t ba = brow + tp * 16 * (K1S * 2) + kt * 32;
            ldsm_x4(ba, bh);
            ldsm_x4(ba + 38912, bl);
            mma_bf16(acc[2 * tpl],     ah, bh[0], bh[2]);
            mma_bf16(acc[2 * tpl + 1], ah, bh[1], bh[3]);
            mma_bf16(acc[2 * tpl],     ah, bl[0], bl[2]);
            mma_bf16(acc[2 * tpl + 1], ah, bl[1], bl[3]);
            mma_bf16(acc[2 * tpl],     al, bh[0], bh[2]);
            mma_bf16(acc[2 * tpl + 1], al, bh[1], bh[3]);
        }
    }

    // epilogue: +b0, masked sum(y^2), store y scratch + bf16x2 noise scratch
    const int gr = lane >> 2, qc = (lane & 3) * 2;
    const long r0g = (long)blk * 128 + rg * 16 + gr;
    const bool v0 = r0g < NPOINTS, v1 = (r0g + 8) < NPOINTS;
    double ls = 0.0;
    float2* gy2 = (float2*)g_y;
    const size_t tb = ((size_t)(blk * 16 + w)) * 8 * 64;
#pragma unroll
    for (int nt = 0; nt < 8; ++nt) {
        int colg = (nh * 8 + nt) * 8 + qc;
        float c0 = acc[nt][0] + sb0[colg];
        float c1 = acc[nt][1] + sb0[colg + 1];
        float c2 = acc[nt][2] + sb0[colg];
        float c3 = acc[nt][3] + sb0[colg + 1];
        if (v0) ls += (double)c0 * c0 + (double)c1 * c1;
        if (v1) ls += (double)c2 * c2 + (double)c3 * c3;
        gy2[tb + nt * 64 + lane]      = make_float2(c0, c1);
        gy2[tb + nt * 64 + 32 + lane] = make_float2(c2, c3);
        // noise for the same 4 elements (index = row*128 + col)
        uint32_t fb0 = (uint32_t)(r0g * 128) + colg;
        float n0 = noise_at(fb0),        n1 = noise_at(fb0 + 1);
        float n2 = noise_at(fb0 + 1024), n3 = noise_at(fb0 + 1025);
        g_n[tb + nt * 64 + lane]      = packbf2(n0, n1);
        g_n[tb + nt * 64 + 32 + lane] = packbf2(n2, n3);
    }
#pragma unroll
    for (int off = 16; off; off >>= 1) ls += __shfl_down_sync(0xffffffffu, ls, off);
    if (lane == 0) sRed[w] = ls;
    __syncthreads();
    if (w == 0) {
        double v = (lane < 16) ? sRed[lane] : 0.0;
#pragma unroll
        for (int off = 8; off; off >>= 1) v += __shfl_down_sync(0xffffffffu, v, off);
        if (lane == 0) g_part[blk] = v;
    }
}

// ------------------------------------------------------- deterministic sum ---
__global__ void reduce_kernel() {
    __shared__ double s[256];
    double v = 0.0;
    for (int i = threadIdx.x; i < NBLK; i += 256) v += g_part[i];
    s[threadIdx.x] = v;
    __syncthreads();
    for (int o = 128; o > 0; o >>= 1) {
        if (threadIdx.x < o) s[threadIdx.x] += s[threadIdx.x + o];
        __syncthreads();
    }
    if (threadIdx.x == 0) g_sumsq = s[0];
}

// ------------------------------------------------------------------- pass2 ---
__global__ void __launch_bounds__(TPB, 1)
pass2_kernel(const float* __restrict__ b1, const float* __restrict__ b2,
             const float* __restrict__ b3, const float* __restrict__ W4,
             const float* __restrict__ b4, float* __restrict__ out) {
    float* sBias = (float*)(smem + P2_BIAS);
    float* sW4 = (float*)(smem + P2_W4);
    float* sb4 = (float*)(smem + P2_B4);
    float* exch = (float*)(smem + P2_EXCH);
    const uint32_t sb = smem_u32(smem);

    const int tid = threadIdx.x;
    const int w = tid >> 5, lane = tid & 31;
    const int rg = w >> 1, nh = w & 1;
    const int gr = lane >> 2, qc = (lane & 3) * 2;
    const int blk = blockIdx.x;

    if (tid < 128) { sBias[tid] = b1[tid]; sBias[128 + tid] = b2[tid]; sBias[256 + tid] = b3[tid]; }
    if (tid < 256) sW4[tid] = W4[tid];
    if (tid < 2) sb4[tid] = b4[tid];

    double ss = g_sumsq;
    float power = (float)(ss * (1.0 / 128000000.0));
    float stdv = 0.0f;
    if (isfinite(power) && power > 1.1920929e-07f) stdv = sqrtf(power * 1e-3f);

    // build A = tanh(y + stdv*noise) hi/lo (noise preloaded bf16x2)
    {
        uint32_t* aHi = (uint32_t*)(smem + P2_A);
        uint32_t* aLo = aHi + 34816 / 4;
        const float2* gy2 = (const float2*)g_y;
        const size_t tb = ((size_t)(blk * 16 + w)) * 8 * 64;
#pragma unroll 2
        for (int nt = 0; nt < 8; ++nt) {
#pragma unroll
            for (int h = 0; h < 2; ++h) {
                float2 y = gy2[tb + nt * 64 + h * 32 + lane];
                uint32_t un = g_n[tb + nt * 64 + h * 32 + lane];
                float n0 = __uint_as_float(un << 16);
                float n1 = __uint_as_float(un & 0xffff0000u);
                int row = rg * 16 + gr + 8 * h;
                float v0 = fast_tanh(fmaf(n0, stdv, y.x));
                float v1 = fast_tanh(fmaf(n1, stdv, y.y));
                uint32_t hp, lp;
                split2(v0, v1, hp, lp);
                aHi[row * (K2S / 2) + (nh * 8 + nt) * 4 + (lane & 3)] = hp;
                aLo[row * (K2S / 2) + (nh * 8 + nt) * 4 + (lane & 3)] = lp;
            }
        }
    }

    const uint32_t arow = sb + P2_A + (rg * 16 + (lane & 15)) * (K2S * 2) + (lane >> 4) * 16;
    const uint32_t brow = sb + P2_W + (lane & 15) * (K2S * 2) + (lane >> 4) * 16;
    float acc[8][4];

#pragma unroll 1
    for (int L = 0; L < 3; ++L) {
        // stage W(L) hi/lo (69632 B); also orders prior A writes before mma reads
        {
            const float4* src = (const float4*)g_wimg[L];
            float4* dst = (float4*)(smem + P2_W);
            for (int i = tid; i < 69632 / 16; i += TPB) dst[i] = src[i];
        }
        __syncthreads();

#pragma unroll
        for (int t = 0; t < 8; ++t)
#pragma unroll
            for (int i = 0; i < 4; ++i) acc[t][i] = 0.f;

#pragma unroll 1
        for (int kt = 0; kt < 8; ++kt) {
            uint32_t ah[4], al[4];
            ldsm_x4(arow + kt * 32, ah);
            ldsm_x4(arow + kt * 32 + 34816, al);
#pragma unroll
            for (int tpl = 0; tpl < 4; ++tpl) {
                int tp = nh * 4 + tpl;
                uint32_t bh[4], bl[4];
                uint32_t ba = brow + tp * 16 * (K2S * 2) + kt * 32;
                ldsm_x4(ba, bh);
                ldsm_x4(ba + 34816, bl);
                mma_bf16(acc[2 * tpl],     ah, bh[0], bh[2]);
                mma_bf16(acc[2 * tpl + 1], ah, bh[1], bh[3]);
                mma_bf16(acc[2 * tpl],     ah, bl[0], bl[2]);
                mma_bf16(acc[2 * tpl + 1], ah, bl[1], bl[3]);
                mma_bf16(acc[2 * tpl],     al, bh[0], bh[2]);
                mma_bf16(acc[2 * tpl + 1], al, bh[1], bh[3]);
            }
        }
        __syncthreads();   // all A/W reads done before A rewrite / next staging

        if (L < 2) {
            uint32_t* aHi = (uint32_t*)(smem + P2_A);
            uint32_t* aLo = aHi + 34816 / 4;
#pragma unroll
            for (int nt = 0; nt < 8; ++nt) {
                int colg = (nh * 8 + nt) * 8 + qc;
#pragma unroll
                for (int h = 0; h < 2; ++h) {
                    float v0 = fast_tanh(acc[nt][2 * h]     + sBias[L * 128 + colg]);
                    float v1 = fast_tanh(acc[nt][2 * h + 1] + sBias[L * 128 + colg + 1]);
                    uint32_t hp, lp;
                    split2(v0, v1, hp, lp);
                    int row = rg * 16 + gr + 8 * h;
                    aHi[row * (K2S / 2) + (nh * 8 + nt) * 4 + (lane & 3)] = hp;
                    aLo[row * (K2S / 2) + (nh * 8 + nt) * 4 + (lane & 3)] = lp;
                }
            }
        }
    }

    // final activations + output partials over this warp's 64 cols
    float p00 = 0.f, p01 = 0.f, p10 = 0.f, p11 = 0.f;
#pragma unroll
    for (int nt = 0; nt < 8; ++nt) {
#pragma unroll
        for (int i = 0; i < 2; ++i) {
            int col = (nh * 8 + nt) * 8 + qc + i;
            float b = sBias[256 + col];
            float h0 = fast_tanh(acc[nt][i] + b);
            float h1 = fast_tanh(acc[nt][2 + i] + b);
            float w0 = sW4[col], w1 = sW4[128 + col];
            p00 = fmaf(h0, w0, p00); p01 = fmaf(h0, w1, p01);
            p10 = fmaf(h1, w0, p10); p11 = fmaf(h1, w1, p11);
        }
    }
#pragma unroll
    for (int m = 1; m <= 2; m <<= 1) {
        p00 += __shfl_xor_sync(0xffffffffu, p00, m);
        p01 += __shfl_xor_sync(0xffffffffu, p01, m);
        p10 += __shfl_xor_sync(0xffffffffu, p10, m);
        p11 += __shfl_xor_sync(0xffffffffu, p11, m);
    }
    if ((lane & 3) == 0) {
        int row0 = rg * 16 + gr;
        exch[(row0 * 2 + nh) * 2 + 0] = p00;
        exch[(row0 * 2 + nh) * 2 + 1] = p01;
        exch[((row0 + 8) * 2 + nh) * 2 + 0] = p10;
        exch[((row0 + 8) * 2 + nh) * 2 + 1] = p11;
    }
    __syncthreads();
    if (tid < 256) {
        int row = tid >> 1, o = tid & 1;
        long rowg = (long)blk * 128 + row;
        if (rowg < NPOINTS)
            out[rowg * 2 + o] = exch[(row * 2 + 0) * 2 + o] + exch[(row * 2 + 1) * 2 + o] + sb4[o];
    }
}

// ------------------------------------------------------------------- host ----
extern "C" void kernel_launch(void* const* d_in, const int* in_sizes, int n_in,
                              void* d_out, int out_size) {
    const float* X  = (const float*)d_in[0];
    const float* FB = (const float*)d_in[1];
    const float* W0 = (const float*)d_in[2];
    const float* b0 = (const float*)d_in[3];
    const float* W1 = (const float*)d_in[4];
    const float* b1 = (const float*)d_in[5];
    const float* W2 = (const float*)d_in[6];
    const float* b2 = (const float*)d_in[7];
    const float* W3 = (const float*)d_in[8];
    const float* b3 = (const float*)d_in[9];
    const float* W4 = (const float*)d_in[10];
    const float* b4 = (const float*)d_in[11];
    float* out = (float*)d_out;

    cudaFuncSetAttribute(pass1_kernel, cudaFuncAttributeMaxDynamicSharedMemorySize, P1_SMEM);
    cudaFuncSetAttribute(pass2_kernel, cudaFuncAttributeMaxDynamicSharedMemorySize, P2_SMEM);

    prep_img_kernel<<<64, 256>>>(W0, W1, W2, W3);
    pass1_kernel<<<NBLK, TPB, P1_SMEM>>>(X, FB, b0);
    reduce_kernel<<<1, 256>>>();
    pass2_kernel<<<NBLK, TPB, P2_SMEM>>>(b1, b2, b3, W4, b4, out);
}

// round 9
// speedup vs baseline: 2.4349x; 1.0539x over previous
#include <cuda_runtime.h>
#include <cuda_bf16.h>
#include <cstdint>
#include <math.h>

// ----------------------------------------------------------------------------
// SimplePINN forward on GB300 (base sm_103) — HMMA bf16 split-2, 3-pass.
// R9: pass2 retiled to 64-row CTAs (107KB smem) -> 2 CTAs/SM, 32 warps,
//     occ 25->50%. Warp = 16 rows x 32 cols. pass1/noise layout unchanged;
//     pass2 remaps into pass1's warp-ownership scratch layout.
// ----------------------------------------------------------------------------

#define NPOINTS 1000000
#define NBLK    7813          // pass1: ceil(1e6/128)
#define NBLK2   15625         // pass2: 1e6/64 exact
#define TPB     512

#define K1S 152               // pass1 A/W row stride in bf16 (K=144 pad)
#define K2S 136               // pass2 A/W row stride in bf16 (K=128 pad)

// pass1 smem layout (bytes)
#define P1_RED  0             // 16 doubles
#define P1_B0   128
#define P1_FB   640
#define P1_A    1152          // A_hi (38912) then A_lo (38912)
#define P1_W    78976         // W_hi (38912) then W_lo (38912)
#define P1_SMEM 156800
// pass2 smem layout (64-row tile)
#define P2_BIAS 0             // 384 f
#define P2_W4   1536          // 256 f
#define P2_B4   2560          // 2 f
#define P2_EXCH 2576          // 512 f
#define P2_A    4736          // A_hi (17408) then A_lo (17408)
#define P2_W    39552         // W_hi (34816) then W_lo (34816)
#define P2_SMEM 109184

__device__ __align__(16) __nv_bfloat16 g_w0img[2][128 * K1S];
__device__ __align__(16) __nv_bfloat16 g_wimg[3][2][128 * K2S];
__device__ float    g_y[(size_t)NBLK * 16384];
__device__ uint32_t g_n[(size_t)NBLK * 8192];    // bf16x2-packed noise
__device__ double g_part[NBLK];
__device__ double g_sumsq;

extern __shared__ __align__(16) char smem[];

// ------------------------------------------------------------ ptx helpers ---
__device__ __forceinline__ uint32_t smem_u32(const void* p) {
    uint32_t a;
    asm("{ .reg .u64 t; cvta.to.shared.u64 t, %1; cvt.u32.u64 %0, t; }" : "=r"(a) : "l"(p));
    return a;
}
__device__ __forceinline__ void ldsm_x4(uint32_t addr, uint32_t r[4]) {
    asm volatile("ldmatrix.sync.aligned.m8n8.x4.shared.b16 {%0,%1,%2,%3}, [%4];"
                 : "=r"(r[0]), "=r"(r[1]), "=r"(r[2]), "=r"(r[3]) : "r"(addr));
}
__device__ __forceinline__ void mma_bf16(float* c, const uint32_t* a, uint32_t b0, uint32_t b1) {
    asm volatile("mma.sync.aligned.m16n8k16.row.col.f32.bf16.bf16.f32 "
                 "{%0,%1,%2,%3}, {%4,%5,%6,%7}, {%8,%9}, {%0,%1,%2,%3};"
                 : "+f"(c[0]), "+f"(c[1]), "+f"(c[2]), "+f"(c[3])
                 : "r"(a[0]), "r"(a[1]), "r"(a[2]), "r"(a[3]), "r"(b0), "r"(b1));
}

// ---------------------------------------------------------------- threefry ---
__device__ __forceinline__ uint32_t rotl32(uint32_t x, int r) { return __funnelshift_l(x, x, r); }
__device__ __forceinline__ uint32_t threefry_bits(uint32_t idx) {
    const uint32_t k0 = 0u, k1 = 42u;
    const uint32_t k2 = k0 ^ k1 ^ 0x1BD11BDAu;
    uint32_t x0 = 0u + k0, x1 = idx + k1;
#define TFR(r) { x0 += x1; x1 = rotl32(x1, r); x1 ^= x0; }
    TFR(13) TFR(15) TFR(26) TFR(6)   x0 += k1; x1 += k2 + 1u;
    TFR(17) TFR(29) TFR(16) TFR(24)  x0 += k2; x1 += k0 + 2u;
    TFR(13) TFR(15) TFR(26) TFR(6)   x0 += k0; x1 += k1 + 3u;
    TFR(17) TFR(29) TFR(16) TFR(24)  x0 += k1; x1 += k2 + 4u;
    TFR(13) TFR(15) TFR(26) TFR(6)   x0 += k2; x1 += k0 + 5u;
#undef TFR
    return x0 ^ x1;
}
__device__ __forceinline__ float erfinv_xla(float x) {
    float w = -__logf(fmaf(-x, x, 1.0f));
    float p;
    if (w < 5.0f) {
        w -= 2.5f;
        p = 2.81022636e-08f;
        p = fmaf(p, w, 3.43273939e-07f);  p = fmaf(p, w, -3.5233877e-06f);
        p = fmaf(p, w, -4.39150654e-06f); p = fmaf(p, w, 0.00021858087f);
        p = fmaf(p, w, -0.00125372503f);  p = fmaf(p, w, -0.00417768164f);
        p = fmaf(p, w, 0.246640727f);     p = fmaf(p, w, 1.50140941f);
    } else {
        w = sqrtf(w) - 3.0f;
        p = -0.000200214257f;
        p = fmaf(p, w, 0.000100950558f);  p = fmaf(p, w, 0.00134934322f);
        p = fmaf(p, w, -0.00367342844f);  p = fmaf(p, w, 0.00573950773f);
        p = fmaf(p, w, -0.0076224613f);   p = fmaf(p, w, 0.00943887047f);
        p = fmaf(p, w, 1.00167406f);      p = fmaf(p, w, 2.83297682f);
    }
    return p * x;
}
__device__ __forceinline__ float noise_at(uint32_t flat) {
    uint32_t bits = threefry_bits(flat);
    float u01 = __uint_as_float((bits >> 9) | 0x3F800000u) - 1.0f;
    const float lo = -0.99999994f;
    float u = fmaxf(lo, fmaf(u01, 1.99999994f, lo));
    return 1.4142135381698608f * erfinv_xla(u);
}
__device__ __forceinline__ float fast_tanh(float x) {
    float e = __expf(2.0f * x);
    return 1.0f - __fdividef(2.0f, e + 1.0f);
}

// ------------------------------------------------------------ bf16 split ----
__device__ __forceinline__ void split2(float f0, float f1, uint32_t& hp, uint32_t& lp) {
    __nv_bfloat16 h0 = __float2bfloat16_rn(f0), h1 = __float2bfloat16_rn(f1);
    float l0 = f0 - __bfloat162float(h0), l1 = f1 - __bfloat162float(h1);
    __nv_bfloat16 g0 = __float2bfloat16_rn(l0), g1 = __float2bfloat16_rn(l1);
    hp = ((uint32_t)__bfloat16_as_ushort(h1) << 16) | __bfloat16_as_ushort(h0);
    lp = ((uint32_t)__bfloat16_as_ushort(g1) << 16) | __bfloat16_as_ushort(g0);
}
__device__ __forceinline__ uint32_t packbf2(float f0, float f1) {
    __nv_bfloat16 h0 = __float2bfloat16_rn(f0), h1 = __float2bfloat16_rn(f1);
    return ((uint32_t)__bfloat16_as_ushort(h1) << 16) | __bfloat16_as_ushort(h0);
}

// -------------------------------------------------------------------- prep ---
__global__ void prep_img_kernel(const float* __restrict__ W0, const float* __restrict__ W1,
                                const float* __restrict__ W2, const float* __restrict__ W3) {
    int i0 = blockIdx.x * blockDim.x + threadIdx.x;
    int st = gridDim.x * blockDim.x;
    for (int idx = i0; idx < 128 * K1S; idx += st) {
        int n = idx / K1S, k = idx - n * K1S;
        float v = (k < 130) ? W0[n * 130 + k] : 0.f;
        __nv_bfloat16 h = __float2bfloat16_rn(v);
        g_w0img[0][idx] = h;
        g_w0img[1][idx] = __float2bfloat16_rn(v - __bfloat162float(h));
    }
    for (int L = 0; L < 3; ++L) {
        const float* W = (L == 0) ? W1 : (L == 1) ? W2 : W3;
        for (int idx = i0; idx < 128 * K2S; idx += st) {
            int n = idx / K2S, k = idx - n * K2S;
            float v = (k < 128) ? W[n * 128 + k] : 0.f;
            __nv_bfloat16 h = __float2bfloat16_rn(v);
            g_wimg[L][0][idx] = h;
            g_wimg[L][1][idx] = __float2bfloat16_rn(v - __bfloat162float(h));
        }
    }
}

// ------------------------------------------------------------------- pass1 ---
__device__ __forceinline__ float feat_val(int k, float x0, float x1, const float* sFB) {
    if (k < 2) return (k == 0) ? x0 : x1;
    if (k < 130) {
        int j = (k < 66) ? (k - 2) : (k - 66);
        float t = fmaf(x1, sFB[64 + j], x0 * sFB[j]);
        float fr = t - rintf(t);
        return (k < 66) ? sinpif(2.0f * fr) : cospif(2.0f * fr);
    }
    return 0.f;
}

__global__ void __launch_bounds__(TPB, 1)
pass1_kernel(const float* __restrict__ X, const float* __restrict__ FB,
             const float* __restrict__ b0v) {
    double* sRed = (double*)(smem + P1_RED);
    float* sb0 = (float*)(smem + P1_B0);
    float* sFB = (float*)(smem + P1_FB);
    const uint32_t sb = smem_u32(smem);

    const int tid = threadIdx.x;
    const int w = tid >> 5, lane = tid & 31;
    const int rg = w >> 1, nh = w & 1;          // row-group 0..7, n-half 0..1
    const int blk = blockIdx.x;

    if (tid < 128) { sb0[tid] = b0v[tid]; sFB[tid] = FB[tid]; }
    // stage W0 hi/lo (77824 B)
    {
        const float4* src = (const float4*)g_w0img;
        float4* dst = (float4*)(smem + P1_W);
        for (int i = tid; i < 77824 / 16; i += TPB) dst[i] = src[i];
    }
    // build feats A hi/lo (4 threads per row, 18 col-pairs each)
    {
        int row = tid >> 2, q = tid & 3;
        long rowg = (long)blk * 128 + row;
        float x0 = 0.f, x1 = 0.f;
        if (rowg < NPOINTS) { float2 xv = ((const float2*)X)[rowg]; x0 = xv.x; x1 = xv.y; }
        uint32_t* aHi = (uint32_t*)(smem + P1_A);
        uint32_t* aLo = aHi + 38912 / 4;
        int cp0 = q * 18;
#pragma unroll 6
        for (int cp = cp0; cp < cp0 + 18; ++cp) {
            float f0 = feat_val(2 * cp, x0, x1, sFB);
            float f1 = feat_val(2 * cp + 1, x0, x1, sFB);
            uint32_t hp, lp;
            split2(f0, f1, hp, lp);
            aHi[row * (K1S / 2) + cp] = hp;
            aLo[row * (K1S / 2) + cp] = lp;
        }
    }
    __syncthreads();

    float acc[8][4];
#pragma unroll
    for (int t = 0; t < 8; ++t)
#pragma unroll
        for (int i = 0; i < 4; ++i) acc[t][i] = 0.f;

    const uint32_t arow = sb + P1_A + (rg * 16 + (lane & 15)) * (K1S * 2) + (lane >> 4) * 16;
    const uint32_t brow = sb + P1_W + (lane & 15) * (K1S * 2) + (lane >> 4) * 16;
#pragma unroll 1
    for (int kt = 0; kt < 9; ++kt) {
        uint32_t ah[4], al[4];
        ldsm_x4(arow + kt * 32, ah);
        ldsm_x4(arow + kt * 32 + 38912, al);
#pragma unroll
        for (int tpl = 0; tpl < 4; ++tpl) {
            int tp = nh * 4 + tpl;
            uint32_t bh[4], bl[4];
            uint32_t ba = brow + tp * 16 * (K1S * 2) + kt * 32;
            ldsm_x4(ba, bh);
            ldsm_x4(ba + 38912, bl);
            mma_bf16(acc[2 * tpl],     ah, bh[0], bh[2]);
            mma_bf16(acc[2 * tpl + 1], ah, bh[1], bh[3]);
            mma_bf16(acc[2 * tpl],     ah, bl[0], bl[2]);
            mma_bf16(acc[2 * tpl + 1], ah, bl[1], bl[3]);
            mma_bf16(acc[2 * tpl],     al, bh[0], bh[2]);
            mma_bf16(acc[2 * tpl + 1], al, bh[1], bh[3]);
        }
    }

    // epilogue: +b0, masked sum(y^2), store y scratch + bf16x2 noise scratch
    const int gr = lane >> 2, qc = (lane & 3) * 2;
    const long r0g = (long)blk * 128 + rg * 16 + gr;
    const bool v0 = r0g < NPOINTS, v1 = (r0g + 8) < NPOINTS;
    double ls = 0.0;
    float2* gy2 = (float2*)g_y;
    const size_t tb = ((size_t)(blk * 16 + w)) * 8 * 64;
#pragma unroll
    for (int nt = 0; nt < 8; ++nt) {
        int colg = (nh * 8 + nt) * 8 + qc;
        float c0 = acc[nt][0] + sb0[colg];
        float c1 = acc[nt][1] + sb0[colg + 1];
        float c2 = acc[nt][2] + sb0[colg];
        float c3 = acc[nt][3] + sb0[colg + 1];
        if (v0) ls += (double)c0 * c0 + (double)c1 * c1;
        if (v1) ls += (double)c2 * c2 + (double)c3 * c3;
        gy2[tb + nt * 64 + lane]      = make_float2(c0, c1);
        gy2[tb + nt * 64 + 32 + lane] = make_float2(c2, c3);
        uint32_t fb0 = (uint32_t)(r0g * 128) + colg;
        float n0 = noise_at(fb0),        n1 = noise_at(fb0 + 1);
        float n2 = noise_at(fb0 + 1024), n3 = noise_at(fb0 + 1025);
        g_n[tb + nt * 64 + lane]      = packbf2(n0, n1);
        g_n[tb + nt * 64 + 32 + lane] = packbf2(n2, n3);
    }
#pragma unroll
    for (int off = 16; off; off >>= 1) ls += __shfl_down_sync(0xffffffffu, ls, off);
    if (lane == 0) sRed[w] = ls;
    __syncthreads();
    if (w == 0) {
        double v = (lane < 16) ? sRed[lane] : 0.0;
#pragma unroll
        for (int off = 8; off; off >>= 1) v += __shfl_down_sync(0xffffffffu, v, off);
        if (lane == 0) g_part[blk] = v;
    }
}

// ------------------------------------------------------- deterministic sum ---
__global__ void reduce_kernel() {
    __shared__ double s[256];
    double v = 0.0;
    for (int i = threadIdx.x; i < NBLK; i += 256) v += g_part[i];
    s[threadIdx.x] = v;
    __syncthreads();
    for (int o = 128; o > 0; o >>= 1) {
        if (threadIdx.x < o) s[threadIdx.x] += s[threadIdx.x + o];
        __syncthreads();
    }
    if (threadIdx.x == 0) g_sumsq = s[0];
}

// ------------------------------------------------------------------- pass2 ---
// 64-row tile, 512 threads = 16 warps; warp = 16 rows x 32 cols:
//   rg = w>>2 (0..3) row-group, nq = w&3 (0..3) col-quarter.
__global__ void __launch_bounds__(TPB, 2)
pass2_kernel(const float* __restrict__ b1, const float* __restrict__ b2,
             const float* __restrict__ b3, const float* __restrict__ W4,
             const float* __restrict__ b4, float* __restrict__ out) {
    float* sBias = (float*)(smem + P2_BIAS);
    float* sW4 = (float*)(smem + P2_W4);
    float* sb4 = (float*)(smem + P2_B4);
    float* exch = (float*)(smem + P2_EXCH);
    const uint32_t sb = smem_u32(smem);

    const int tid = threadIdx.x;
    const int w = tid >> 5, lane = tid & 31;
    const int rg = w >> 2, nq = w & 3;
    const int gr = lane >> 2, qc = (lane & 3) * 2;
    const int blk = blockIdx.x;

    if (tid < 128) { sBias[tid] = b1[tid]; sBias[128 + tid] = b2[tid]; sBias[256 + tid] = b3[tid]; }
    if (tid < 256) sW4[tid] = W4[tid];
    if (tid < 2) sb4[tid] = b4[tid];

    double ss = g_sumsq;
    float power = (float)(ss * (1.0 / 128000000.0));
    float stdv = 0.0f;
    if (isfinite(power) && power > 1.1920929e-07f) stdv = sqrtf(power * 1e-3f);

    // build A = tanh(y + stdv*noise) hi/lo from pass1's warp-ownership scratch
    {
        uint32_t* aHi = (uint32_t*)(smem + P2_A);
        uint32_t* aLo = aHi + 17408 / 4;
        const float2* gy2 = (const float2*)g_y;
        const int blk1 = blk >> 1;
        const int w1 = ((blk & 1) * 4 + rg) * 2 + (nq >> 1);
        const size_t tb = ((size_t)(blk1 * 16 + w1)) * 8 * 64;
#pragma unroll
        for (int nt2 = 0; nt2 < 4; ++nt2) {
            int nt1 = (nq & 1) * 4 + nt2;
#pragma unroll
            for (int h = 0; h < 2; ++h) {
                size_t idx = tb + nt1 * 64 + h * 32 + lane;
                float2 y = gy2[idx];
                uint32_t un = g_n[idx];
                float n0 = __uint_as_float(un << 16);
                float n1 = __uint_as_float(un & 0xffff0000u);
                int row = rg * 16 + gr + 8 * h;
                float v0 = fast_tanh(fmaf(n0, stdv, y.x));
                float v1 = fast_tanh(fmaf(n1, stdv, y.y));
                uint32_t hp, lp;
                split2(v0, v1, hp, lp);
                int acol = nq * 16 + nt2 * 4 + (lane & 3);
                aHi[row * (K2S / 2) + acol] = hp;
                aLo[row * (K2S / 2) + acol] = lp;
            }
        }
    }

    const uint32_t arow = sb + P2_A + (rg * 16 + (lane & 15)) * (K2S * 2) + (lane >> 4) * 16;
    const uint32_t brow = sb + P2_W + (lane & 15) * (K2S * 2) + (lane >> 4) * 16;
    float acc[4][4];

#pragma unroll 1
    for (int L = 0; L < 3; ++L) {
        // stage W(L) hi/lo (69632 B); sync also orders A writes before mma reads
        {
            const float4* src = (const float4*)g_wimg[L];
            float4* dst = (float4*)(smem + P2_W);
            for (int i = tid; i < 69632 / 16; i += TPB) dst[i] = src[i];
        }
        __syncthreads();

#pragma unroll
        for (int t = 0; t < 4; ++t)
#pragma unroll
            for (int i = 0; i < 4; ++i) acc[t][i] = 0.f;

#pragma unroll 1
        for (int kt = 0; kt < 8; ++kt) {
            uint32_t ah[4], al[4];
            ldsm_x4(arow + kt * 32, ah);
            ldsm_x4(arow + kt * 32 + 17408, al);
#pragma unroll
            for (int tpl = 0; tpl < 2; ++tpl) {
                int tp = nq * 2 + tpl;
                uint32_t bh[4], bl[4];
                uint32_t ba = brow + tp * 16 * (K2S * 2) + kt * 32;
                ldsm_x4(ba, bh);
                ldsm_x4(ba + 34816, bl);
                mma_bf16(acc[2 * tpl],     ah, bh[0], bh[2]);
                mma_bf16(acc[2 * tpl + 1], ah, bh[1], bh[3]);
                mma_bf16(acc[2 * tpl],     ah, bl[0], bl[2]);
                mma_bf16(acc[2 * tpl + 1], ah, bl[1], bl[3]);
                mma_bf16(acc[2 * tpl],     al, bh[0], bh[2]);
                mma_bf16(acc[2 * tpl + 1], al, bh[1], bh[3]);
            }
        }
        __syncthreads();   // all A/W reads done before A rewrite / next staging

        if (L < 2) {
            uint32_t* aHi = (uint32_t*)(smem + P2_A);
            uint32_t* aLo = aHi + 17408 / 4;
#pragma unroll
            for (int nt2 = 0; nt2 < 4; ++nt2) {
                int colg = nq * 32 + nt2 * 8 + qc;
#pragma unroll
                for (int h = 0; h < 2; ++h) {
                    float v0 = fast_tanh(acc[nt2][2 * h]     + sBias[L * 128 + colg]);
                    float v1 = fast_tanh(acc[nt2][2 * h + 1] + sBias[L * 128 + colg + 1]);
                    uint32_t hp, lp;
                    split2(v0, v1, hp, lp);
                    int row = rg * 16 + gr + 8 * h;
                    int acol = nq * 16 + nt2 * 4 + (lane & 3);
                    aHi[row * (K2S / 2) + acol] = hp;
                    aLo[row * (K2S / 2) + acol] = lp;
                }
            }
        }
    }

    // final activations + output partials over this warp's 32 cols
    float p00 = 0.f, p01 = 0.f, p10 = 0.f, p11 = 0.f;
#pragma unroll
    for (int nt2 = 0; nt2 < 4; ++nt2) {
#pragma unroll
        for (int i = 0; i < 2; ++i) {
            int col = nq * 32 + nt2 * 8 + qc + i;
            float b = sBias[256 + col];
            float h0 = fast_tanh(acc[nt2][i] + b);
            float h1 = fast_tanh(acc[nt2][2 + i] + b);
            float w0 = sW4[col], w1 = sW4[128 + col];
            p00 = fmaf(h0, w0, p00); p01 = fmaf(h0, w1, p01);
            p10 = fmaf(h1, w0, p10); p11 = fmaf(h1, w1, p11);
        }
    }
#pragma unroll
    for (int m = 1; m <= 2; m <<= 1) {
        p00 += __shfl_xor_sync(0xffffffffu, p00, m);
        p01 += __shfl_xor_sync(0xffffffffu, p01, m);
        p10 += __shfl_xor_sync(0xffffffffu, p10, m);
        p11 += __shfl_xor_sync(0xffffffffu, p11, m);
    }
    if ((lane & 3) == 0) {
        int row0 = rg * 16 + gr;
        exch[(row0 * 4 + nq) * 2 + 0] = p00;
        exch[(row0 * 4 + nq) * 2 + 1] = p01;
        exch[((row0 + 8) * 4 + nq) * 2 + 0] = p10;
        exch[((row0 + 8) * 4 + nq) * 2 + 1] = p11;
    }
    __syncthreads();
    if (tid < 128) {
        int row = tid >> 1, o = tid & 1;
        long rowg = (long)blk * 64 + row;
        float v = exch[(row * 4 + 0) * 2 + o] + exch[(row * 4 + 1) * 2 + o]
                + exch[(row * 4 + 2) * 2 + o] + exch[(row * 4 + 3) * 2 + o] + sb4[o];
        out[rowg * 2 + o] = v;
    }
}

// ------------------------------------------------------------------- host ----
extern "C" void kernel_launch(void* const* d_in, const int* in_sizes, int n_in,
                              void* d_out, int out_size) {
    const float* X  = (const float*)d_in[0];
    const float* FB = (const float*)d_in[1];
    const float* W0 = (const float*)d_in[2];
    const float* b0 = (const float*)d_in[3];
    const float* W1 = (const float*)d_in[4];
    const float* b1 = (const float*)d_in[5];
    const float* W2 = (const float*)d_in[6];
    const float* b2 = (const float*)d_in[7];
    const float* W3 = (const float*)d_in[8];
    const float* b3 = (const float*)d_in[9];
    const float* W4 = (const float*)d_in[10];
    const float* b4 = (const float*)d_in[11];
    float* out = (float*)d_out;

    cudaFuncSetAttribute(pass1_kernel, cudaFuncAttributeMaxDynamicSharedMemorySize, P1_SMEM);
    cudaFuncSetAttribute(pass2_kernel, cudaFuncAttributeMaxDynamicSharedMemorySize, P2_SMEM);

    prep_img_kernel<<<64, 256>>>(W0, W1, W2, W3);
    pass1_kernel<<<NBLK, TPB, P1_SMEM>>>(X, FB, b0);
    reduce_kernel<<<1, 256>>>();
    pass2_kernel<<<NBLK2, TPB, P2_SMEM>>>(b1, b2, b3, W4, b4, out);
}

// round 10
// speedup vs baseline: 2.9470x; 1.2103x over previous
#include <cuda_runtime.h>
#include <cuda_bf16.h>
#include <cstdint>
#include <math.h>

// ----------------------------------------------------------------------------
// SimplePINN forward on GB300 (base sm_103) — HMMA bf16 split-2, 3-pass.
// R10: pass1 retiled to 64-row CTAs (105KB smem -> 2 CTAs/SM) by doing the
//      layer-0 MMA over K=128 and adding feature cols 128/129 as an fp32
//      rank-2 epilogue update. pass1/pass2 now share tile geometry and the
//      scratch layout needs no remap.
// ----------------------------------------------------------------------------

#define NPOINTS 1000000
#define NBLK2   15625         // 1e6/64 exact (both passes)
#define TPB     512

#define K2S 136               // A/W row stride in bf16 (K=128 pad, 17x16B)

// pass1 smem layout (bytes)
#define P1_RED  0             // 16 doubles
#define P1_B0   128           // 128 f
#define P1_FB   640           // 128 f
#define P1_X2   1152          // 128 f  (A cols 128/129, fp32)
#define P1_W2   1664          // 256 f  (W0 cols 128/129, fp32)
#define P1_A    2688          // A_hi (17408) then A_lo (17408)
#define P1_W    37504         // W_hi (34816) then W_lo (34816)
#define P1_SMEM 107136
// pass2 smem layout (64-row tile)
#define P2_BIAS 0             // 384 f
#define P2_W4   1536          // 256 f
#define P2_B4   2560          // 2 f
#define P2_EXCH 2576          // 512 f
#define P2_A    4736          // A_hi (17408) then A_lo (17408)
#define P2_W    39552         // W_hi (34816) then W_lo (34816)
#define P2_SMEM 109184

__device__ __align__(16) __nv_bfloat16 g_w0img[2][128 * K2S];   // k<128 only
__device__ __align__(16) float g_w0tail[256];                    // W0[:,128:130]
__device__ __align__(16) __nv_bfloat16 g_wimg[3][2][128 * K2S];
__device__ float    g_y[(size_t)NBLK2 * 8192];
__device__ uint32_t g_n[(size_t)NBLK2 * 4096];   // bf16x2-packed noise
__device__ double g_part[NBLK2];
__device__ double g_sumsq;

extern __shared__ __align__(16) char smem[];

// ------------------------------------------------------------ ptx helpers ---
__device__ __forceinline__ uint32_t smem_u32(const void* p) {
    uint32_t a;
    asm("{ .reg .u64 t; cvta.to.shared.u64 t, %1; cvt.u32.u64 %0, t; }" : "=r"(a) : "l"(p));
    return a;
}
__device__ __forceinline__ void ldsm_x4(uint32_t addr, uint32_t r[4]) {
    asm volatile("ldmatrix.sync.aligned.m8n8.x4.shared.b16 {%0,%1,%2,%3}, [%4];"
                 : "=r"(r[0]), "=r"(r[1]), "=r"(r[2]), "=r"(r[3]) : "r"(addr));
}
__device__ __forceinline__ void mma_bf16(float* c, const uint32_t* a, uint32_t b0, uint32_t b1) {
    asm volatile("mma.sync.aligned.m16n8k16.row.col.f32.bf16.bf16.f32 "
                 "{%0,%1,%2,%3}, {%4,%5,%6,%7}, {%8,%9}, {%0,%1,%2,%3};"
                 : "+f"(c[0]), "+f"(c[1]), "+f"(c[2]), "+f"(c[3])
                 : "r"(a[0]), "r"(a[1]), "r"(a[2]), "r"(a[3]), "r"(b0), "r"(b1));
}

// ---------------------------------------------------------------- threefry ---
__device__ __forceinline__ uint32_t rotl32(uint32_t x, int r) { return __funnelshift_l(x, x, r); }
__device__ __forceinline__ uint32_t threefry_bits(uint32_t idx) {
    const uint32_t k0 = 0u, k1 = 42u;
    const uint32_t k2 = k0 ^ k1 ^ 0x1BD11BDAu;
    uint32_t x0 = 0u + k0, x1 = idx + k1;
#define TFR(r) { x0 += x1; x1 = rotl32(x1, r); x1 ^= x0; }
    TFR(13) TFR(15) TFR(26) TFR(6)   x0 += k1; x1 += k2 + 1u;
    TFR(17) TFR(29) TFR(16) TFR(24)  x0 += k2; x1 += k0 + 2u;
    TFR(13) TFR(15) TFR(26) TFR(6)   x0 += k0; x1 += k1 + 3u;
    TFR(17) TFR(29) TFR(16) TFR(24)  x0 += k1; x1 += k2 + 4u;
    TFR(13) TFR(15) TFR(26) TFR(6)   x0 += k2; x1 += k0 + 5u;
#undef TFR
    return x0 ^ x1;
}
__device__ __forceinline__ float erfinv_xla(float x) {
    float w = -__logf(fmaf(-x, x, 1.0f));
    float p;
    if (w < 5.0f) {
        w -= 2.5f;
        p = 2.81022636e-08f;
        p = fmaf(p, w, 3.43273939e-07f);  p = fmaf(p, w, -3.5233877e-06f);
        p = fmaf(p, w, -4.39150654e-06f); p = fmaf(p, w, 0.00021858087f);
        p = fmaf(p, w, -0.00125372503f);  p = fmaf(p, w, -0.00417768164f);
        p = fmaf(p, w, 0.246640727f);     p = fmaf(p, w, 1.50140941f);
    } else {
        w = sqrtf(w) - 3.0f;
        p = -0.000200214257f;
        p = fmaf(p, w, 0.000100950558f);  p = fmaf(p, w, 0.00134934322f);
        p = fmaf(p, w, -0.00367342844f);  p = fmaf(p, w, 0.00573950773f);
        p = fmaf(p, w, -0.0076224613f);   p = fmaf(p, w, 0.00943887047f);
        p = fmaf(p, w, 1.00167406f);      p = fmaf(p, w, 2.83297682f);
    }
    return p * x;
}
__device__ __forceinline__ float noise_at(uint32_t flat) {
    uint32_t bits = threefry_bits(flat);
    float u01 = __uint_as_float((bits >> 9) | 0x3F800000u) - 1.0f;
    const float lo = -0.99999994f;
    float u = fmaxf(lo, fmaf(u01, 1.99999994f, lo));
    return 1.4142135381698608f * erfinv_xla(u);
}
__device__ __forceinline__ float fast_tanh(float x) {
    float e = __expf(2.0f * x);
    return 1.0f - __fdividef(2.0f, e + 1.0f);
}

// ------------------------------------------------------------ bf16 split ----
__device__ __forceinline__ void split2(float f0, float f1, uint32_t& hp, uint32_t& lp) {
    __nv_bfloat16 h0 = __float2bfloat16_rn(f0), h1 = __float2bfloat16_rn(f1);
    float l0 = f0 - __bfloat162float(h0), l1 = f1 - __bfloat162float(h1);
    __nv_bfloat16 g0 = __float2bfloat16_rn(l0), g1 = __float2bfloat16_rn(l1);
    hp = ((uint32_t)__bfloat16_as_ushort(h1) << 16) | __bfloat16_as_ushort(h0);
    lp = ((uint32_t)__bfloat16_as_ushort(g1) << 16) | __bfloat16_as_ushort(g0);
}
__device__ __forceinline__ uint32_t packbf2(float f0, float f1) {
    __nv_bfloat16 h0 = __float2bfloat16_rn(f0), h1 = __float2bfloat16_rn(f1);
    return ((uint32_t)__bfloat16_as_ushort(h1) << 16) | __bfloat16_as_ushort(h0);
}

// -------------------------------------------------------------------- prep ---
__global__ void prep_img_kernel(const float* __restrict__ W0, const float* __restrict__ W1,
                                const float* __restrict__ W2, const float* __restrict__ W3) {
    int i0 = blockIdx.x * blockDim.x + threadIdx.x;
    int st = gridDim.x * blockDim.x;
    for (int idx = i0; idx < 128 * K2S; idx += st) {
        int n = idx / K2S, k = idx - n * K2S;
        float v = (k < 128) ? W0[n * 130 + k] : 0.f;
        __nv_bfloat16 h = __float2bfloat16_rn(v);
        g_w0img[0][idx] = h;
        g_w0img[1][idx] = __float2bfloat16_rn(v - __bfloat162float(h));
    }
    for (int idx = i0; idx < 256; idx += st)
        g_w0tail[idx] = W0[(idx >> 1) * 130 + 128 + (idx & 1)];
    for (int L = 0; L < 3; ++L) {
        const float* W = (L == 0) ? W1 : (L == 1) ? W2 : W3;
        for (int idx = i0; idx < 128 * K2S; idx += st) {
            int n = idx / K2S, k = idx - n * K2S;
            float v = (k < 128) ? W[n * 128 + k] : 0.f;
            __nv_bfloat16 h = __float2bfloat16_rn(v);
            g_wimg[L][0][idx] = h;
            g_wimg[L][1][idx] = __float2bfloat16_rn(v - __bfloat162float(h));
        }
    }
}

// ------------------------------------------------------------------- pass1 ---
__device__ __forceinline__ float feat_val(int k, float x0, float x1, const float* sFB) {
    if (k < 2) return (k == 0) ? x0 : x1;
    if (k < 130) {
        int j = (k < 66) ? (k - 2) : (k - 66);
        float t = fmaf(x1, sFB[64 + j], x0 * sFB[j]);
        float fr = t - rintf(t);
        return (k < 66) ? sinpif(2.0f * fr) : cospif(2.0f * fr);
    }
    return 0.f;
}

// 64-row tile; warp = 16 rows x 32 cols (rg = w>>2, nq = w&3).
__global__ void __launch_bounds__(TPB, 2)
pass1_kernel(const float* __restrict__ X, const float* __restrict__ FB,
             const float* __restrict__ b0v) {
    double* sRed = (double*)(smem + P1_RED);
    float* sb0 = (float*)(smem + P1_B0);
    float* sFB = (float*)(smem + P1_FB);
    float* sX2 = (float*)(smem + P1_X2);
    float* sW2 = (float*)(smem + P1_W2);
    const uint32_t sb = smem_u32(smem);

    const int tid = threadIdx.x;
    const int w = tid >> 5, lane = tid & 31;
    const int rg = w >> 2, nq = w & 3;
    const int gr = lane >> 2, qc = (lane & 3) * 2;
    const int blk = blockIdx.x;

    if (tid < 128) { sb0[tid] = b0v[tid]; sFB[tid] = FB[tid]; }
    if (tid < 256) sW2[tid] = g_w0tail[tid];
    // stage W0 hi/lo (69632 B)
    {
        const float4* src = (const float4*)g_w0img;
        float4* dst = (float4*)(smem + P1_W);
        for (int i = tid; i < 69632 / 16; i += TPB) dst[i] = src[i];
    }
    // build feats A hi/lo (8 threads per row, 8 col-pairs each; cols 0..127)
    {
        int row = tid >> 3, q = tid & 7;
        float2 xv = ((const float2*)X)[blk * 64 + row];
        uint32_t* aHi = (uint32_t*)(smem + P1_A);
        uint32_t* aLo = aHi + 17408 / 4;
        int cp0 = q * 8;
#pragma unroll
        for (int cp = cp0; cp < cp0 + 8; ++cp) {
            float f0 = feat_val(2 * cp, xv.x, xv.y, sFB);
            float f1 = feat_val(2 * cp + 1, xv.x, xv.y, sFB);
            uint32_t hp, lp;
            split2(f0, f1, hp, lp);
            aHi[row * (K2S / 2) + cp] = hp;
            aLo[row * (K2S / 2) + cp] = lp;
        }
    }
    // feature cols 128/129 (fp32 tail)
    if (tid < 128) {
        int row = tid >> 1, c = tid & 1;
        float2 xv = ((const float2*)X)[blk * 64 + row];
        sX2[tid] = feat_val(128 + c, xv.x, xv.y, sFB);
    }
    __syncthreads();

    float acc[4][4];
#pragma unroll
    for (int t = 0; t < 4; ++t)
#pragma unroll
        for (int i = 0; i < 4; ++i) acc[t][i] = 0.f;

    const uint32_t arow = sb + P1_A + (rg * 16 + (lane & 15)) * (K2S * 2) + (lane >> 4) * 16;
    const uint32_t brow = sb + P1_W + (lane & 15) * (K2S * 2) + (lane >> 4) * 16;
#pragma unroll 1
    for (int kt = 0; kt < 8; ++kt) {
        uint32_t ah[4], al[4];
        ldsm_x4(arow + kt * 32, ah);
        ldsm_x4(arow + kt * 32 + 17408, al);
#pragma unroll
        for (int tpl = 0; tpl < 2; ++tpl) {
            int tp = nq * 2 + tpl;
            uint32_t bh[4], bl[4];
            uint32_t ba = brow + tp * 16 * (K2S * 2) + kt * 32;
            ldsm_x4(ba, bh);
            ldsm_x4(ba + 34816, bl);
            mma_bf16(acc[2 * tpl],     ah, bh[0], bh[2]);
            mma_bf16(acc[2 * tpl + 1], ah, bh[1], bh[3]);
            mma_bf16(acc[2 * tpl],     ah, bl[0], bl[2]);
            mma_bf16(acc[2 * tpl + 1], ah, bl[1], bl[3]);
            mma_bf16(acc[2 * tpl],     al, bh[0], bh[2]);
            mma_bf16(acc[2 * tpl + 1], al, bh[1], bh[3]);
        }
    }

    // epilogue: +b0 + fp32 rank-2 tail, sum(y^2), store y + bf16x2 noise
    double ls = 0.0;
    float2* gy2 = (float2*)g_y;
    const size_t tb = ((size_t)(blk * 16 + w)) * 4 * 64;
#pragma unroll
    for (int nt2 = 0; nt2 < 4; ++nt2) {
        int colg = nq * 32 + nt2 * 8 + qc;
        float w00 = sW2[colg * 2], w01 = sW2[colg * 2 + 1];
        float w10 = sW2[colg * 2 + 2], w11 = sW2[colg * 2 + 3];
#pragma unroll
        for (int h = 0; h < 2; ++h) {
            int row = rg * 16 + gr + 8 * h;
            float a0 = sX2[row * 2], a1 = sX2[row * 2 + 1];
            float c0 = acc[nt2][2 * h]     + sb0[colg]     + a0 * w00 + a1 * w01;
            float c1 = acc[nt2][2 * h + 1] + sb0[colg + 1] + a0 * w10 + a1 * w11;
            ls += (double)c0 * c0 + (double)c1 * c1;
            size_t idx = tb + nt2 * 64 + h * 32 + lane;
            gy2[idx] = make_float2(c0, c1);
            uint32_t fb0 = (uint32_t)((blk * 64 + row) * 128) + colg;
            g_n[idx] = packbf2(noise_at(fb0), noise_at(fb0 + 1));
        }
    }
#pragma unroll
    for (int off = 16; off; off >>= 1) ls += __shfl_down_sync(0xffffffffu, ls, off);
    if (lane == 0) sRed[w] = ls;
    __syncthreads();
    if (w == 0) {
        double v = (lane < 16) ? sRed[lane] : 0.0;
#pragma unroll
        for (int off = 8; off; off >>= 1) v += __shfl_down_sync(0xffffffffu, v, off);
        if (lane == 0) g_part[blk] = v;
    }
}

// ------------------------------------------------------- deterministic sum ---
__global__ void reduce_kernel() {
    __shared__ double s[256];
    double v = 0.0;
    for (int i = threadIdx.x; i < NBLK2; i += 256) v += g_part[i];
    s[threadIdx.x] = v;
    __syncthreads();
    for (int o = 128; o > 0; o >>= 1) {
        if (threadIdx.x < o) s[threadIdx.x] += s[threadIdx.x + o];
        __syncthreads();
    }
    if (threadIdx.x == 0) g_sumsq = s[0];
}

// ------------------------------------------------------------------- pass2 ---
// 64-row tile; warp = 16 rows x 32 cols (rg = w>>2, nq = w&3).
__global__ void __launch_bounds__(TPB, 2)
pass2_kernel(const float* __restrict__ b1, const float* __restrict__ b2,
             const float* __restrict__ b3, const float* __restrict__ W4,
             const float* __restrict__ b4, float* __restrict__ out) {
    float* sBias = (float*)(smem + P2_BIAS);
    float* sW4 = (float*)(smem + P2_W4);
    float* sb4 = (float*)(smem + P2_B4);
    float* exch = (float*)(smem + P2_EXCH);
    const uint32_t sb = smem_u32(smem);

    const int tid = threadIdx.x;
    const int w = tid >> 5, lane = tid & 31;
    const int rg = w >> 2, nq = w & 3;
    const int gr = lane >> 2, qc = (lane & 3) * 2;
    const int blk = blockIdx.x;

    if (tid < 128) { sBias[tid] = b1[tid]; sBias[128 + tid] = b2[tid]; sBias[256 + tid] = b3[tid]; }
    if (tid < 256) sW4[tid] = W4[tid];
    if (tid < 2) sb4[tid] = b4[tid];

    double ss = g_sumsq;
    float power = (float)(ss * (1.0 / 128000000.0));
    float stdv = 0.0f;
    if (isfinite(power) && power > 1.1920929e-07f) stdv = sqrtf(power * 1e-3f);

    // build A = tanh(y + stdv*noise) hi/lo (same scratch layout as pass1)
    {
        uint32_t* aHi = (uint32_t*)(smem + P2_A);
        uint32_t* aLo = aHi + 17408 / 4;
        const float2* gy2 = (const float2*)g_y;
        const size_t tb = ((size_t)(blk * 16 + w)) * 4 * 64;
#pragma unroll
        for (int nt2 = 0; nt2 < 4; ++nt2) {
#pragma unroll
            for (int h = 0; h < 2; ++h) {
                size_t idx = tb + nt2 * 64 + h * 32 + lane;
                float2 y = gy2[idx];
                uint32_t un = g_n[idx];
                float n0 = __uint_as_float(un << 16);
                float n1 = __uint_as_float(un & 0xffff0000u);
                int row = rg * 16 + gr + 8 * h;
                float v0 = fast_tanh(fmaf(n0, stdv, y.x));
                float v1 = fast_tanh(fmaf(n1, stdv, y.y));
                uint32_t hp, lp;
                split2(v0, v1, hp, lp);
                int acol = nq * 16 + nt2 * 4 + (lane & 3);
                aHi[row * (K2S / 2) + acol] = hp;
                aLo[row * (K2S / 2) + acol] = lp;
            }
        }
    }

    const uint32_t arow = sb + P2_A + (rg * 16 + (lane & 15)) * (K2S * 2) + (lane >> 4) * 16;
    const uint32_t brow = sb + P2_W + (lane & 15) * (K2S * 2) + (lane >> 4) * 16;
    float acc[4][4];

#pragma unroll 1
    for (int L = 0; L < 3; ++L) {
        // stage W(L) hi/lo (69632 B); sync also orders A writes before mma reads
        {
            const float4* src = (const float4*)g_wimg[L];
            float4* dst = (float4*)(smem + P2_W);
            for (int i = tid; i < 69632 / 16; i += TPB) dst[i] = src[i];
        }
        __syncthreads();

#pragma unroll
        for (int t = 0; t < 4; ++t)
#pragma unroll
            for (int i = 0; i < 4; ++i) acc[t][i] = 0.f;

#pragma unroll 1
        for (int kt = 0; kt < 8; ++kt) {
            uint32_t ah[4], al[4];
            ldsm_x4(arow + kt * 32, ah);
            ldsm_x4(arow + kt * 32 + 17408, al);
#pragma unroll
            for (int tpl = 0; tpl < 2; ++tpl) {
                int tp = nq * 2 + tpl;
                uint32_t bh[4], bl[4];
                uint32_t ba = brow + tp * 16 * (K2S * 2) + kt * 32;
                ldsm_x4(ba, bh);
                ldsm_x4(ba + 34816, bl);
                mma_bf16(acc[2 * tpl],     ah, bh[0], bh[2]);
                mma_bf16(acc[2 * tpl + 1], ah, bh[1], bh[3]);
                mma_bf16(acc[2 * tpl],     ah, bl[0], bl[2]);
                mma_bf16(acc[2 * tpl + 1], ah, bl[1], bl[3]);
                mma_bf16(acc[2 * tpl],     al, bh[0], bh[2]);
                mma_bf16(acc[2 * tpl + 1], al, bh[1], bh[3]);
            }
        }
        __syncthreads();   // all A/W reads done before A rewrite / next staging

        if (L < 2) {
            uint32_t* aHi = (uint32_t*)(smem + P2_A);
            uint32_t* aLo = aHi + 17408 / 4;
#pragma unroll
            for (int nt2 = 0; nt2 < 4; ++nt2) {
                int colg = nq * 32 + nt2 * 8 + qc;
#pragma unroll
                for (int h = 0; h < 2; ++h) {
                    float v0 = fast_tanh(acc[nt2][2 * h]     + sBias[L * 128 + colg]);
                    float v1 = fast_tanh(acc[nt2][2 * h + 1] + sBias[L * 128 + colg + 1]);
                    uint32_t hp, lp;
                    split2(v0, v1, hp, lp);
                    int row = rg * 16 + gr + 8 * h;
                    int acol = nq * 16 + nt2 * 4 + (lane & 3);
                    aHi[row * (K2S / 2) + acol] = hp;
                    aLo[row * (K2S / 2) + acol] = lp;
                }
            }
        }
    }

    // final activations + output partials over this warp's 32 cols
    float p00 = 0.f, p01 = 0.f, p10 = 0.f, p11 = 0.f;
#pragma unroll
    for (int nt2 = 0; nt2 < 4; ++nt2) {
#pragma unroll
        for (int i = 0; i < 2; ++i) {
            int col = nq * 32 + nt2 * 8 + qc + i;
            float b = sBias[256 + col];
            float h0 = fast_tanh(acc[nt2][i] + b);
            float h1 = fast_tanh(acc[nt2][2 + i] + b);
            float w0 = sW4[col], w1 = sW4[128 + col];
            p00 = fmaf(h0, w0, p00); p01 = fmaf(h0, w1, p01);
            p10 = fmaf(h1, w0, p10); p11 = fmaf(h1, w1, p11);
        }
    }
#pragma unroll
    for (int m = 1; m <= 2; m <<= 1) {
        p00 += __shfl_xor_sync(0xffffffffu, p00, m);
        p01 += __shfl_xor_sync(0xffffffffu, p01, m);
        p10 += __shfl_xor_sync(0xffffffffu, p10, m);
        p11 += __shfl_xor_sync(0xffffffffu, p11, m);
    }
    if ((lane & 3) == 0) {
        int row0 = rg * 16 + gr;
        exch[(row0 * 4 + nq) * 2 + 0] = p00;
        exch[(row0 * 4 + nq) * 2 + 1] = p01;
        exch[((row0 + 8) * 4 + nq) * 2 + 0] = p10;
        exch[((row0 + 8) * 4 + nq) * 2 + 1] = p11;
    }
    __syncthreads();
    if (tid < 128) {
        int row = tid >> 1, o = tid & 1;
        long rowg = (long)blk * 64 + row;
        float v = exch[(row * 4 + 0) * 2 + o] + exch[(row * 4 + 1) * 2 + o]
                + exch[(row * 4 + 2) * 2 + o] + exch[(row * 4 + 3) * 2 + o] + sb4[o];
        out[rowg * 2 + o] = v;
    }
}

// ------------------------------------------------------------------- host ----
extern "C" void kernel_launch(void* const* d_in, const int* in_sizes, int n_in,
                              void* d_out, int out_size) {
    const float* X  = (const float*)d_in[0];
    const float* FB = (const float*)d_in[1];
    const float* W0 = (const float*)d_in[2];
    const float* b0 = (const float*)d_in[3];
    const float* W1 = (const float*)d_in[4];
    const float* b1 = (const float*)d_in[5];
    const float* W2 = (const float*)d_in[6];
    const float* b2 = (const float*)d_in[7];
    const float* W3 = (const float*)d_in[8];
    const float* b3 = (const float*)d_in[9];
    const float* W4 = (const float*)d_in[10];
    const float* b4 = (const float*)d_in[11];
    float* out = (float*)d_out;

    cudaFuncSetAttribute(pass1_kernel, cudaFuncAttributeMaxDynamicSharedMemorySize, P1_SMEM);
    cudaFuncSetAttribute(pass2_kernel, cudaFuncAttributeMaxDynamicSharedMemorySize, P2_SMEM);

    prep_img_kernel<<<64, 256>>>(W0, W1, W2, W3);
    pass1_kernel<<<NBLK2, TPB, P1_SMEM>>>(X, FB, b0);
    reduce_kernel<<<1, 256>>>();
    pass2_kernel<<<NBLK2, TPB, P2_SMEM>>>(b1, b2, b3, W4, b4, out);
}

// round 11
// speedup vs baseline: 3.2685x; 1.1091x over previous
#include <cuda_runtime.h>
#include <cuda_bf16.h>
#include <cstdint>
#include <math.h>

// ----------------------------------------------------------------------------
// SimplePINN forward on GB300 (base sm_103) — HMMA bf16 split-2, 3-pass.
// R11: cp.async W staging overlapped with epilogues, tanh.approx, fat reduce.
// ----------------------------------------------------------------------------

#define NPOINTS 1000000
#define NBLK2   15625         // 1e6/64 exact (both passes)
#define TPB     512

#define K2S 136               // A/W row stride in bf16 (K=128 pad, 17x16B)

// pass1 smem layout (bytes)
#define P1_RED  0             // 16 doubles
#define P1_B0   128           // 128 f
#define P1_FB   640           // 128 f
#define P1_X2   1152          // 128 f  (A cols 128/129, fp32)
#define P1_W2   1664          // 256 f  (W0 cols 128/129, fp32)
#define P1_A    2688          // A_hi (17408) then A_lo (17408)
#define P1_W    37504         // W_hi (34816) then W_lo (34816)
#define P1_SMEM 107136
// pass2 smem layout (64-row tile)
#define P2_BIAS 0             // 384 f
#define P2_W4   1536          // 256 f
#define P2_B4   2560          // 2 f
#define P2_EXCH 2576          // 512 f
#define P2_A    4736          // A_hi (17408) then A_lo (17408)
#define P2_W    39552         // W_hi (34816) then W_lo (34816)
#define P2_SMEM 109184

__device__ __align__(16) __nv_bfloat16 g_w0img[2][128 * K2S];   // k<128 only
__device__ __align__(16) float g_w0tail[256];                    // W0[:,128:130]
__device__ __align__(16) __nv_bfloat16 g_wimg[3][2][128 * K2S];
__device__ float    g_y[(size_t)NBLK2 * 8192];
__device__ uint32_t g_n[(size_t)NBLK2 * 4096];   // bf16x2-packed noise
__device__ double g_part[NBLK2];
__device__ double g_sumsq;

extern __shared__ __align__(16) char smem[];

// ------------------------------------------------------------ ptx helpers ---
__device__ __forceinline__ uint32_t smem_u32(const void* p) {
    uint32_t a;
    asm("{ .reg .u64 t; cvta.to.shared.u64 t, %1; cvt.u32.u64 %0, t; }" : "=r"(a) : "l"(p));
    return a;
}
__device__ __forceinline__ void ldsm_x4(uint32_t addr, uint32_t r[4]) {
    asm volatile("ldmatrix.sync.aligned.m8n8.x4.shared.b16 {%0,%1,%2,%3}, [%4];"
                 : "=r"(r[0]), "=r"(r[1]), "=r"(r[2]), "=r"(r[3]) : "r"(addr));
}
__device__ __forceinline__ void mma_bf16(float* c, const uint32_t* a, uint32_t b0, uint32_t b1) {
    asm volatile("mma.sync.aligned.m16n8k16.row.col.f32.bf16.bf16.f32 "
                 "{%0,%1,%2,%3}, {%4,%5,%6,%7}, {%8,%9}, {%0,%1,%2,%3};"
                 : "+f"(c[0]), "+f"(c[1]), "+f"(c[2]), "+f"(c[3])
                 : "r"(a[0]), "r"(a[1]), "r"(a[2]), "r"(a[3]), "r"(b0), "r"(b1));
}
__device__ __forceinline__ void cp_async16(uint32_t dst, const void* src) {
    asm volatile("cp.async.cg.shared.global [%0], [%1], 16;" :: "r"(dst), "l"(src));
}
#define CP_COMMIT() asm volatile("cp.async.commit_group;" ::: "memory")
#define CP_WAIT0()  asm volatile("cp.async.wait_group 0;" ::: "memory")

// ---------------------------------------------------------------- threefry ---
__device__ __forceinline__ uint32_t rotl32(uint32_t x, int r) { return __funnelshift_l(x, x, r); }
__device__ __forceinline__ uint32_t threefry_bits(uint32_t idx) {
    const uint32_t k0 = 0u, k1 = 42u;
    const uint32_t k2 = k0 ^ k1 ^ 0x1BD11BDAu;
    uint32_t x0 = 0u + k0, x1 = idx + k1;
#define TFR(r) { x0 += x1; x1 = rotl32(x1, r); x1 ^= x0; }
    TFR(13) TFR(15) TFR(26) TFR(6)   x0 += k1; x1 += k2 + 1u;
    TFR(17) TFR(29) TFR(16) TFR(24)  x0 += k2; x1 += k0 + 2u;
    TFR(13) TFR(15) TFR(26) TFR(6)   x0 += k0; x1 += k1 + 3u;
    TFR(17) TFR(29) TFR(16) TFR(24)  x0 += k1; x1 += k2 + 4u;
    TFR(13) TFR(15) TFR(26) TFR(6)   x0 += k2; x1 += k0 + 5u;
#undef TFR
    return x0 ^ x1;
}
__device__ __forceinline__ float erfinv_xla(float x) {
    float w = -__logf(fmaf(-x, x, 1.0f));
    float p;
    if (w < 5.0f) {
        w -= 2.5f;
        p = 2.81022636e-08f;
        p = fmaf(p, w, 3.43273939e-07f);  p = fmaf(p, w, -3.5233877e-06f);
        p = fmaf(p, w, -4.39150654e-06f); p = fmaf(p, w, 0.00021858087f);
        p = fmaf(p, w, -0.00125372503f);  p = fmaf(p, w, -0.00417768164f);
        p = fmaf(p, w, 0.246640727f);     p = fmaf(p, w, 1.50140941f);
    } else {
        w = sqrtf(w) - 3.0f;
        p = -0.000200214257f;
        p = fmaf(p, w, 0.000100950558f);  p = fmaf(p, w, 0.00134934322f);
        p = fmaf(p, w, -0.00367342844f);  p = fmaf(p, w, 0.00573950773f);
        p = fmaf(p, w, -0.0076224613f);   p = fmaf(p, w, 0.00943887047f);
        p = fmaf(p, w, 1.00167406f);      p = fmaf(p, w, 2.83297682f);
    }
    return p * x;
}
__device__ __forceinline__ float noise_at(uint32_t flat) {
    uint32_t bits = threefry_bits(flat);
    float u01 = __uint_as_float((bits >> 9) | 0x3F800000u) - 1.0f;
    const float lo = -0.99999994f;
    float u = fmaxf(lo, fmaf(u01, 1.99999994f, lo));
    return 1.4142135381698608f * erfinv_xla(u);
}
__device__ __forceinline__ float fast_tanh(float x) {
    float y;
    asm("tanh.approx.f32 %0, %1;" : "=f"(y) : "f"(x));
    return y;
}

// ------------------------------------------------------------ bf16 split ----
__device__ __forceinline__ void split2(float f0, float f1, uint32_t& hp, uint32_t& lp) {
    __nv_bfloat16 h0 = __float2bfloat16_rn(f0), h1 = __float2bfloat16_rn(f1);
    float l0 = f0 - __bfloat162float(h0), l1 = f1 - __bfloat162float(h1);
    __nv_bfloat16 g0 = __float2bfloat16_rn(l0), g1 = __float2bfloat16_rn(l1);
    hp = ((uint32_t)__bfloat16_as_ushort(h1) << 16) | __bfloat16_as_ushort(h0);
    lp = ((uint32_t)__bfloat16_as_ushort(g1) << 16) | __bfloat16_as_ushort(g0);
}
__device__ __forceinline__ uint32_t packbf2(float f0, float f1) {
    __nv_bfloat16 h0 = __float2bfloat16_rn(f0), h1 = __float2bfloat16_rn(f1);
    return ((uint32_t)__bfloat16_as_ushort(h1) << 16) | __bfloat16_as_ushort(h0);
}

// -------------------------------------------------------------------- prep ---
__global__ void prep_img_kernel(const float* __restrict__ W0, const float* __restrict__ W1,
                                const float* __restrict__ W2, const float* __restrict__ W3) {
    int i0 = blockIdx.x * blockDim.x + threadIdx.x;
    int st = gridDim.x * blockDim.x;
    for (int idx = i0; idx < 128 * K2S; idx += st) {
        int n = idx / K2S, k = idx - n * K2S;
        float v = (k < 128) ? W0[n * 130 + k] : 0.f;
        __nv_bfloat16 h = __float2bfloat16_rn(v);
        g_w0img[0][idx] = h;
        g_w0img[1][idx] = __float2bfloat16_rn(v - __bfloat162float(h));
    }
    for (int idx = i0; idx < 256; idx += st)
        g_w0tail[idx] = W0[(idx >> 1) * 130 + 128 + (idx & 1)];
    for (int L = 0; L < 3; ++L) {
        const float* W = (L == 0) ? W1 : (L == 1) ? W2 : W3;
        for (int idx = i0; idx < 128 * K2S; idx += st) {
            int n = idx / K2S, k = idx - n * K2S;
            float v = (k < 128) ? W[n * 128 + k] : 0.f;
            __nv_bfloat16 h = __float2bfloat16_rn(v);
            g_wimg[L][0][idx] = h;
            g_wimg[L][1][idx] = __float2bfloat16_rn(v - __bfloat162float(h));
        }
    }
}

// ------------------------------------------------------------------- pass1 ---
__device__ __forceinline__ float feat_val(int k, float x0, float x1, const float* sFB) {
    if (k < 2) return (k == 0) ? x0 : x1;
    if (k < 130) {
        int j = (k < 66) ? (k - 2) : (k - 66);
        float t = fmaf(x1, sFB[64 + j], x0 * sFB[j]);
        float fr = t - rintf(t);
        return (k < 66) ? sinpif(2.0f * fr) : cospif(2.0f * fr);
    }
    return 0.f;
}

// 64-row tile; warp = 16 rows x 32 cols (rg = w>>2, nq = w&3).
__global__ void __launch_bounds__(TPB, 2)
pass1_kernel(const float* __restrict__ X, const float* __restrict__ FB,
             const float* __restrict__ b0v) {
    double* sRed = (double*)(smem + P1_RED);
    float* sb0 = (float*)(smem + P1_B0);
    float* sFB = (float*)(smem + P1_FB);
    float* sX2 = (float*)(smem + P1_X2);
    float* sW2 = (float*)(smem + P1_W2);
    const uint32_t sb = smem_u32(smem);

    const int tid = threadIdx.x;
    const int w = tid >> 5, lane = tid & 31;
    const int rg = w >> 2, nq = w & 3;
    const int gr = lane >> 2, qc = (lane & 3) * 2;
    const int blk = blockIdx.x;

    // stage W0 hi/lo (69632 B) via cp.async — overlaps feats build below
    {
        const float4* src = (const float4*)g_w0img;
        for (int i = tid; i < 69632 / 16; i += TPB)
            cp_async16(sb + P1_W + i * 16, src + i);
        CP_COMMIT();
    }
    if (tid < 128) { sb0[tid] = b0v[tid]; sFB[tid] = FB[tid]; }
    if (tid < 256) sW2[tid] = g_w0tail[tid];
    __syncthreads();   // sFB visible for feats build
    // build feats A hi/lo (8 threads per row, 8 col-pairs each; cols 0..127)
    {
        int row = tid >> 3, q = tid & 7;
        float2 xv = ((const float2*)X)[blk * 64 + row];
        uint32_t* aHi = (uint32_t*)(smem + P1_A);
        uint32_t* aLo = aHi + 17408 / 4;
        int cp0 = q * 8;
#pragma unroll
        for (int cp = cp0; cp < cp0 + 8; ++cp) {
            float f0 = feat_val(2 * cp, xv.x, xv.y, sFB);
            float f1 = feat_val(2 * cp + 1, xv.x, xv.y, sFB);
            uint32_t hp, lp;
            split2(f0, f1, hp, lp);
            aHi[row * (K2S / 2) + cp] = hp;
            aLo[row * (K2S / 2) + cp] = lp;
        }
    }
    // feature cols 128/129 (fp32 tail)
    if (tid < 128) {
        int row = tid >> 1, c = tid & 1;
        float2 xv = ((const float2*)X)[blk * 64 + row];
        sX2[tid] = feat_val(128 + c, xv.x, xv.y, sFB);
    }
    CP_WAIT0();
    __syncthreads();

    float acc[4][4];
#pragma unroll
    for (int t = 0; t < 4; ++t)
#pragma unroll
        for (int i = 0; i < 4; ++i) acc[t][i] = 0.f;

    const uint32_t arow = sb + P1_A + (rg * 16 + (lane & 15)) * (K2S * 2) + (lane >> 4) * 16;
    const uint32_t brow = sb + P1_W + (lane & 15) * (K2S * 2) + (lane >> 4) * 16;
#pragma unroll 1
    for (int kt = 0; kt < 8; ++kt) {
        uint32_t ah[4], al[4];
        ldsm_x4(arow + kt * 32, ah);
        ldsm_x4(arow + kt * 32 + 17408, al);
#pragma unroll
        for (int tpl = 0; tpl < 2; ++tpl) {
            int tp = nq * 2 + tpl;
            uint32_t bh[4], bl[4];
            uint32_t ba = brow + tp * 16 * (K2S * 2) + kt * 32;
            ldsm_x4(ba, bh);
            ldsm_x4(ba + 34816, bl);
            mma_bf16(acc[2 * tpl],     ah, bh[0], bh[2]);
            mma_bf16(acc[2 * tpl + 1], ah, bh[1], bh[3]);
            mma_bf16(acc[2 * tpl],     ah, bl[0], bl[2]);
            mma_bf16(acc[2 * tpl + 1], ah, bl[1], bl[3]);
            mma_bf16(acc[2 * tpl],     al, bh[0], bh[2]);
            mma_bf16(acc[2 * tpl + 1], al, bh[1], bh[3]);
        }
    }

    // epilogue: +b0 + fp32 rank-2 tail, sum(y^2), store y + bf16x2 noise
    double ls = 0.0;
    float2* gy2 = (float2*)g_y;
    const size_t tb = ((size_t)(blk * 16 + w)) * 4 * 64;
#pragma unroll
    for (int nt2 = 0; nt2 < 4; ++nt2) {
        int colg = nq * 32 + nt2 * 8 + qc;
        float w00 = sW2[colg * 2], w01 = sW2[colg * 2 + 1];
        float w10 = sW2[colg * 2 + 2], w11 = sW2[colg * 2 + 3];
#pragma unroll
        for (int h = 0; h < 2; ++h) {
            int row = rg * 16 + gr + 8 * h;
            float a0 = sX2[row * 2], a1 = sX2[row * 2 + 1];
            float c0 = acc[nt2][2 * h]     + sb0[colg]     + a0 * w00 + a1 * w01;
            float c1 = acc[nt2][2 * h + 1] + sb0[colg + 1] + a0 * w10 + a1 * w11;
            ls += (double)c0 * c0 + (double)c1 * c1;
            size_t idx = tb + nt2 * 64 + h * 32 + lane;
            gy2[idx] = make_float2(c0, c1);
            uint32_t fb0 = (uint32_t)((blk * 64 + row) * 128) + colg;
            g_n[idx] = packbf2(noise_at(fb0), noise_at(fb0 + 1));
        }
    }
#pragma unroll
    for (int off = 16; off; off >>= 1) ls += __shfl_down_sync(0xffffffffu, ls, off);
    if (lane == 0) sRed[w] = ls;
    __syncthreads();
    if (w == 0) {
        double v = (lane < 16) ? sRed[lane] : 0.0;
#pragma unroll
        for (int off = 8; off; off >>= 1) v += __shfl_down_sync(0xffffffffu, v, off);
        if (lane == 0) g_part[blk] = v;
    }
}

// ------------------------------------------------------- deterministic sum ---
__global__ void reduce_kernel() {
    __shared__ double s[1024];
    double v = 0.0;
    for (int i = threadIdx.x; i < NBLK2; i += 1024) v += g_part[i];
    s[threadIdx.x] = v;
    __syncthreads();
    for (int o = 512; o > 0; o >>= 1) {
        if (threadIdx.x < o) s[threadIdx.x] += s[threadIdx.x + o];
        __syncthreads();
    }
    if (threadIdx.x == 0) g_sumsq = s[0];
}

// ------------------------------------------------------------------- pass2 ---
// 64-row tile; warp = 16 rows x 32 cols (rg = w>>2, nq = w&3).
__global__ void __launch_bounds__(TPB, 2)
pass2_kernel(const float* __restrict__ b1, const float* __restrict__ b2,
             const float* __restrict__ b3, const float* __restrict__ W4,
             const float* __restrict__ b4, float* __restrict__ out) {
    float* sBias = (float*)(smem + P2_BIAS);
    float* sW4 = (float*)(smem + P2_W4);
    float* sb4 = (float*)(smem + P2_B4);
    float* exch = (float*)(smem + P2_EXCH);
    const uint32_t sb = smem_u32(smem);

    const int tid = threadIdx.x;
    const int w = tid >> 5, lane = tid & 31;
    const int rg = w >> 2, nq = w & 3;
    const int gr = lane >> 2, qc = (lane & 3) * 2;
    const int blk = blockIdx.x;

    // kick off W(0) staging immediately (overlaps A-build)
    {
        const float4* src = (const float4*)g_wimg[0];
        for (int i = tid; i < 69632 / 16; i += TPB)
            cp_async16(sb + P2_W + i * 16, src + i);
        CP_COMMIT();
    }
    if (tid < 128) { sBias[tid] = b1[tid]; sBias[128 + tid] = b2[tid]; sBias[256 + tid] = b3[tid]; }
    if (tid < 256) sW4[tid] = W4[tid];
    if (tid < 2) sb4[tid] = b4[tid];

    double ss = g_sumsq;
    float power = (float)(ss * (1.0 / 128000000.0));
    float stdv = 0.0f;
    if (isfinite(power) && power > 1.1920929e-07f) stdv = sqrtf(power * 1e-3f);

    // build A = tanh(y + stdv*noise) hi/lo (same scratch layout as pass1)
    {
        uint32_t* aHi = (uint32_t*)(smem + P2_A);
        uint32_t* aLo = aHi + 17408 / 4;
        const float2* gy2 = (const float2*)g_y;
        const size_t tb = ((size_t)(blk * 16 + w)) * 4 * 64;
#pragma unroll
        for (int nt2 = 0; nt2 < 4; ++nt2) {
#pragma unroll
            for (int h = 0; h < 2; ++h) {
                size_t idx = tb + nt2 * 64 + h * 32 + lane;
                float2 y = gy2[idx];
                uint32_t un = g_n[idx];
                float n0 = __uint_as_float(un << 16);
                float n1 = __uint_as_float(un & 0xffff0000u);
                int row = rg * 16 + gr + 8 * h;
                float v0 = fast_tanh(fmaf(n0, stdv, y.x));
                float v1 = fast_tanh(fmaf(n1, stdv, y.y));
                uint32_t hp, lp;
                split2(v0, v1, hp, lp);
                int acol = nq * 16 + nt2 * 4 + (lane & 3);
                aHi[row * (K2S / 2) + acol] = hp;
                aLo[row * (K2S / 2) + acol] = lp;
            }
        }
    }

    const uint32_t arow = sb + P2_A + (rg * 16 + (lane & 15)) * (K2S * 2) + (lane >> 4) * 16;
    const uint32_t brow = sb + P2_W + (lane & 15) * (K2S * 2) + (lane >> 4) * 16;
    float acc[4][4];

#pragma unroll 1
    for (int L = 0; L < 3; ++L) {
        CP_WAIT0();          // W(L) staged
        __syncthreads();     // + A writes visible

#pragma unroll
        for (int t = 0; t < 4; ++t)
#pragma unroll
            for (int i = 0; i < 4; ++i) acc[t][i] = 0.f;

#pragma unroll 1
        for (int kt = 0; kt < 8; ++kt) {
            uint32_t ah[4], al[4];
            ldsm_x4(arow + kt * 32, ah);
            ldsm_x4(arow + kt * 32 + 17408, al);
#pragma unroll
            for (int tpl = 0; tpl < 2; ++tpl) {
                int tp = nq * 2 + tpl;
                uint32_t bh[4], bl[4];
                uint32_t ba = brow + tp * 16 * (K2S * 2) + kt * 32;
                ldsm_x4(ba, bh);
                ldsm_x4(ba + 34816, bl);
                mma_bf16(acc[2 * tpl],     ah, bh[0], bh[2]);
                mma_bf16(acc[2 * tpl + 1], ah, bh[1], bh[3]);
                mma_bf16(acc[2 * tpl],     ah, bl[0], bl[2]);
                mma_bf16(acc[2 * tpl + 1], ah, bl[1], bl[3]);
                mma_bf16(acc[2 * tpl],     al, bh[0], bh[2]);
                mma_bf16(acc[2 * tpl + 1], al, bh[1], bh[3]);
            }
        }
        __syncthreads();   // all A/W reads done before A rewrite / W restage

        if (L < 2) {
            // start W(L+1) staging now — overlaps the epilogue below
            {
                const float4* src = (const float4*)g_wimg[L + 1];
                for (int i = tid; i < 69632 / 16; i += TPB)
                    cp_async16(sb + P2_W + i * 16, src + i);
                CP_COMMIT();
            }
            uint32_t* aHi = (uint32_t*)(smem + P2_A);
            uint32_t* aLo = aHi + 17408 / 4;
#pragma unroll
            for (int nt2 = 0; nt2 < 4; ++nt2) {
                int colg = nq * 32 + nt2 * 8 + qc;
#pragma unroll
                for (int h = 0; h < 2; ++h) {
                    float v0 = fast_tanh(acc[nt2][2 * h]     + sBias[L * 128 + colg]);
                    float v1 = fast_tanh(acc[nt2][2 * h + 1] + sBias[L * 128 + colg + 1]);
                    uint32_t hp, lp;
                    split2(v0, v1, hp, lp);
                    int row = rg * 16 + gr + 8 * h;
                    int acol = nq * 16 + nt2 * 4 + (lane & 3);
                    aHi[row * (K2S / 2) + acol] = hp;
                    aLo[row * (K2S / 2) + acol] = lp;
                }
            }
        }
    }

    // final activations + output partials over this warp's 32 cols
    float p00 = 0.f, p01 = 0.f, p10 = 0.f, p11 = 0.f;
#pragma unroll
    for (int nt2 = 0; nt2 < 4; ++nt2) {
#pragma unroll
        for (int i = 0; i < 2; ++i) {
            int col = nq * 32 + nt2 * 8 + qc + i;
            float b = sBias[256 + col];
            float h0 = fast_tanh(acc[nt2][i] + b);
            float h1 = fast_tanh(acc[nt2][2 + i] + b);
            float w0 = sW4[col], w1 = sW4[128 + col];
            p00 = fmaf(h0, w0, p00); p01 = fmaf(h0, w1, p01);
            p10 = fmaf(h1, w0, p10); p11 = fmaf(h1, w1, p11);
        }
    }
#pragma unroll
    for (int m = 1; m <= 2; m <<= 1) {
        p00 += __shfl_xor_sync(0xffffffffu, p00, m);
        p01 += __shfl_xor_sync(0xffffffffu, p01, m);
        p10 += __shfl_xor_sync(0xffffffffu, p10, m);
        p11 += __shfl_xor_sync(0xffffffffu, p11, m);
    }
    if ((lane & 3) == 0) {
        int row0 = rg * 16 + gr;
        exch[(row0 * 4 + nq) * 2 + 0] = p00;
        exch[(row0 * 4 + nq) * 2 + 1] = p01;
        exch[((row0 + 8) * 4 + nq) * 2 + 0] = p10;
        exch[((row0 + 8) * 4 + nq) * 2 + 1] = p11;
    }
    __syncthreads();
    if (tid < 128) {
        int row = tid >> 1, o = tid & 1;
        long rowg = (long)blk * 64 + row;
        float v = exch[(row * 4 + 0) * 2 + o] + exch[(row * 4 + 1) * 2 + o]
                + exch[(row * 4 + 2) * 2 + o] + exch[(row * 4 + 3) * 2 + o] + sb4[o];
        out[rowg * 2 + o] = v;
    }
}

// ------------------------------------------------------------------- host ----
extern "C" void kernel_launch(void* const* d_in, const int* in_sizes, int n_in,
                              void* d_out, int out_size) {
    const float* X  = (const float*)d_in[0];
    const float* FB = (const float*)d_in[1];
    const float* W0 = (const float*)d_in[2];
    const float* b0 = (const float*)d_in[3];
    const float* W1 = (const float*)d_in[4];
    const float* b1 = (const float*)d_in[5];
    const float* W2 = (const float*)d_in[6];
    const float* b2 = (const float*)d_in[7];
    const float* W3 = (const float*)d_in[8];
    const float* b3 = (const float*)d_in[9];
    const float* W4 = (const float*)d_in[10];
    const float* b4 = (const float*)d_in[11];
    float* out = (float*)d_out;

    cudaFuncSetAttribute(pass1_kernel, cudaFuncAttributeMaxDynamicSharedMemorySize, P1_SMEM);
    cudaFuncSetAttribute(pass2_kernel, cudaFuncAttributeMaxDynamicSharedMemorySize, P2_SMEM);

    prep_img_kernel<<<64, 256>>>(W0, W1, W2, W3);
    pass1_kernel<<<NBLK2, TPB, P1_SMEM>>>(X, FB, b0);
    reduce_kernel<<<1, 1024>>>();
    pass2_kernel<<<NBLK2, TPB, P2_SMEM>>>(b1, b2, b3, W4, b4, out);
}